// round 13
// baseline (speedup 1.0000x reference)
#include <cuda_runtime.h>
#include <cuda_bf16.h>
#include <cstdint>

#define BATCH 4
#define CH    256
#define CQK   32
#define NN    4096

#define TQ     128
#define TJ     64
#define NTILES (NN / TJ)   // 64

// ---- unified KV tile (bf16 elements): [KH 64x40][KL 64x40][VH 256x64][VL 256x64]
#define KPAD       40
#define KV_TILE_EL 37888
#define KV_TILE_B  75776
#define KH_OFF     0
#define KL_OFF     5120
#define V_OFF      10240
#define SM_MB0  0
#define SM_MB1  8
#define SM_BUF  1024
#define SM_TOTAL (SM_BUF + 2 * KV_TILE_B)   // 152576

// GEMM kernels SMEM: [mbar pad 1024][B_hi 64KB][B_lo 64KB]
#define GEMM_SM_TOTAL (1024 + 2 * 65536)

// ---------------- scratch (device globals; no allocation allowed) ----------
__device__ __nv_bfloat16 g_qh[(size_t)BATCH * NN * CQK];
__device__ __nv_bfloat16 g_ql[(size_t)BATCH * NN * CQK];
__device__ __align__(128) __nv_bfloat16 g_kv[(size_t)BATCH * NTILES * KV_TILE_EL];
__device__ __align__(128) __nv_bfloat16 g_aoh[(size_t)BATCH * NN * CH];  // swizzled
__device__ __align__(128) __nv_bfloat16 g_aol[(size_t)BATCH * NN * CH];
__device__ __align__(128) __nv_bfloat16 g_xh[(size_t)BATCH * NN * CH];   // x^T swizzled
__device__ __align__(128) __nv_bfloat16 g_xl[(size_t)BATCH * NN * CH];
__device__ __nv_bfloat16 g_wgh[CH * CH];
__device__ __nv_bfloat16 g_wgl[CH * CH];
__device__ __nv_bfloat16 g_wh[320 * CH];   // [wv;wq;wk] hi
__device__ __nv_bfloat16 g_wl[320 * CH];
__device__ float         g_bqkv[320];

// ---------------- helpers ---------------------------------------------------
__device__ __forceinline__ unsigned cvt_bf16x2(float hi, float lo) {
    unsigned r;
    asm("cvt.rn.bf16x2.f32 %0, %1, %2;" : "=r"(r) : "f"(hi), "f"(lo));
    return r;
}
__device__ __forceinline__ float f_lo(unsigned u) { return __uint_as_float(u << 16); }
__device__ __forceinline__ float f_hi(unsigned u) { return __uint_as_float(u & 0xffff0000u); }

__device__ __forceinline__ uint32_t smem_u32(const void* p) {
    uint32_t a;
    asm("{ .reg .u64 t; cvta.to.shared.u64 t, %1; cvt.u32.u64 %0, t; }"
        : "=r"(a) : "l"(p));
    return a;
}

#define MBAR_INIT(addr, cnt) \
    asm volatile("mbarrier.init.shared.b64 [%0], %1;" :: "r"(addr), "r"(cnt) : "memory")
#define MBAR_EXPECT_TX(addr, bytes) \
    asm volatile("mbarrier.arrive.expect_tx.shared.b64 _, [%0], %1;" \
                 :: "r"(addr), "r"(bytes) : "memory")

__device__ __forceinline__ void mbar_wait(uint32_t addr, uint32_t parity) {
    asm volatile(
        "{\n\t.reg .pred P;\n\t"
        "WL_%=:\n\t"
        "mbarrier.try_wait.parity.acquire.cta.shared::cta.b64 P, [%0], %1, 0x989680;\n\t"
        "@P bra WD_%=;\n\t"
        "bra WL_%=;\n\t"
        "WD_%=:\n\t}"
        :: "r"(addr), "r"(parity) : "memory");
}
__device__ __forceinline__ void bulk_g2s(uint32_t dst, const void* src,
                                         uint32_t bytes, uint32_t mbar) {
    asm volatile(
        "cp.async.bulk.shared::cluster.global.mbarrier::complete_tx::bytes "
        "[%0], [%1], %2, [%3];"
        :: "r"(dst), "l"(src), "r"(bytes), "r"(mbar) : "memory");
}

__device__ __forceinline__ void ldsm4(unsigned& r0, unsigned& r1,
                                      unsigned& r2, unsigned& r3, uint32_t a) {
    asm volatile("ldmatrix.sync.aligned.m8n8.x4.shared.b16 {%0,%1,%2,%3}, [%4];"
                 : "=r"(r0), "=r"(r1), "=r"(r2), "=r"(r3) : "r"(a));
}

__device__ __forceinline__ void mma_bf16(float* d, const unsigned* a,
                                         unsigned b0, unsigned b1) {
    asm volatile(
        "mma.sync.aligned.m16n8k16.row.col.f32.bf16.bf16.f32 "
        "{%0,%1,%2,%3}, {%4,%5,%6,%7}, {%8,%9}, {%0,%1,%2,%3};"
        : "+f"(d[0]), "+f"(d[1]), "+f"(d[2]), "+f"(d[3])
        : "r"(a[0]), "r"(a[1]), "r"(a[2]), "r"(a[3]), "r"(b0), "r"(b1));
}

// load A fragments (weights) for k-slice ks
__device__ __forceinline__ void load_a_frags(
    unsigned ah[2][4], unsigned al[2][4],
    const __nv_bfloat16* wh, const __nv_bfloat16* wl,
    int c0, int g, int t, int ks)
{
#pragma unroll
    for (int mb = 0; mb < 2; mb++) {
        int cr  = c0 + mb * 16 + g;
        int col = ks * 16 + t * 2;
        ah[mb][0] = *(const unsigned*)(wh + cr * CH + col);
        ah[mb][1] = *(const unsigned*)(wh + (cr + 8) * CH + col);
        ah[mb][2] = *(const unsigned*)(wh + cr * CH + col + 8);
        ah[mb][3] = *(const unsigned*)(wh + (cr + 8) * CH + col + 8);
        al[mb][0] = *(const unsigned*)(wl + cr * CH + col);
        al[mb][1] = *(const unsigned*)(wl + (cr + 8) * CH + col);
        al[mb][2] = *(const unsigned*)(wl + cr * CH + col + 8);
        al[mb][3] = *(const unsigned*)(wl + (cr + 8) * CH + col + 8);
    }
}

// 12 MMAs for one p-group
#define GEMM_P_GROUP(d, ah, al, bh0, bh1, bh2, bh3, bl0, bl1, bl2, bl3, p) \
    do {                                                                   \
        mma_bf16(d[0][2*(p)],     ah[0], bh0, bh1);                        \
        mma_bf16(d[0][2*(p) + 1], ah[0], bh2, bh3);                        \
        mma_bf16(d[1][2*(p)],     ah[1], bh0, bh1);                        \
        mma_bf16(d[1][2*(p) + 1], ah[1], bh2, bh3);                        \
        mma_bf16(d[0][2*(p)],     ah[0], bl0, bl1);                        \
        mma_bf16(d[0][2*(p) + 1], ah[0], bl2, bl3);                        \
        mma_bf16(d[1][2*(p)],     ah[1], bl0, bl1);                        \
        mma_bf16(d[1][2*(p) + 1], ah[1], bl2, bl3);                        \
        mma_bf16(d[0][2*(p)],     al[0], bh0, bh1);                        \
        mma_bf16(d[0][2*(p) + 1], al[0], bh2, bh3);                        \
        mma_bf16(d[1][2*(p)],     al[1], bh0, bh1);                        \
        mma_bf16(d[1][2*(p) + 1], al[1], bh2, bh3);                        \
    } while (0)

// ============================================================================
// Kernel P0: wg -> bf16 hi/lo
// ============================================================================
__global__ void __launch_bounds__(256)
wgprep_kernel(const float* __restrict__ wg)
{
    int i = blockIdx.x * 256 + threadIdx.x;
    float a = wg[2 * i], b = wg[2 * i + 1];
    unsigned h = cvt_bf16x2(b, a);
    unsigned l = cvt_bf16x2(b - f_hi(h), a - f_lo(h));
    *(unsigned*)(g_wgh + 2 * i) = h;
    *(unsigned*)(g_wgl + 2 * i) = l;
}

// ============================================================================
// Kernel P1: stacked [wv;wq;wk] -> bf16 hi/lo + combined bias
// ============================================================================
__global__ void __launch_bounds__(256)
wqkvprep_kernel(const float* __restrict__ wv, const float* __restrict__ bv,
                const float* __restrict__ wq, const float* __restrict__ bq,
                const float* __restrict__ wk, const float* __restrict__ bk)
{
    int i = blockIdx.x * 256 + threadIdx.x;
    int row  = i >> 7;
    int col2 = (i & 127) * 2;
    const float* src = (row < 256) ? wv + row * CH
                     : (row < 288) ? wq + (row - 256) * CH
                                   : wk + (row - 288) * CH;
    float a = src[col2], b = src[col2 + 1];
    unsigned h = cvt_bf16x2(b, a);
    unsigned l = cvt_bf16x2(b - f_hi(h), a - f_lo(h));
    *(unsigned*)(g_wh + row * CH + col2) = h;
    *(unsigned*)(g_wl + row * CH + col2) = l;
    if (i < 320)
        g_bqkv[i] = (i < 256) ? bv[i] : (i < 288) ? bq[i - 256] : bk[i - 288];
}

// ============================================================================
// Kernel P2: x [b][c][n] fp32 -> x^T [b][n][c] bf16 hi/lo, ldmatrix-swizzled
// ============================================================================
__global__ void __launch_bounds__(256)
xprep_kernel(const float* __restrict__ x)
{
    __shared__ __align__(16) float xs[CH * 33];
    const int b   = blockIdx.y;
    const int n0  = blockIdx.x * 32;
    const int tid = threadIdx.x;

    const float* xb = x + (size_t)b * CH * NN + n0;
    for (int idx = tid; idx < CH * 32; idx += 256) {
        int c = idx >> 5, n = idx & 31;
        xs[c * 33 + n] = xb[(size_t)c * NN + n];
    }
    __syncthreads();

    const int n   = tid & 31;
    const int g3  = tid >> 5;
    const int nsw = (n0 + n) & 7;
    __nv_bfloat16* dh = g_xh + ((size_t)b * NN + n0 + n) * CH;
    __nv_bfloat16* dl = g_xl + ((size_t)b * NN + n0 + n) * CH;

#pragma unroll
    for (int cc = 0; cc < 4; cc++) {
        int ch = g3 * 4 + cc;
        float v[8];
#pragma unroll
        for (int j = 0; j < 8; j++) v[j] = xs[(ch * 8 + j) * 33 + n];
        unsigned h[4], l[4];
#pragma unroll
        for (int j = 0; j < 4; j++) {
            h[j] = cvt_bf16x2(v[2 * j + 1], v[2 * j]);
            l[j] = cvt_bf16x2(v[2 * j + 1] - f_hi(h[j]), v[2 * j] - f_lo(h[j]));
        }
        int mch = (ch ^ nsw) << 3;
        *(uint4*)(dh + mch) = make_uint4(h[0], h[1], h[2], h[3]);
        *(uint4*)(dl + mch) = make_uint4(l[0], l[1], l[2], l[3]);
    }
}

// ============================================================================
// Kernel P3: fused q/k/v projection via HMMA (unchanged from R11)
// ============================================================================
__global__ void __launch_bounds__(320, 1)
qkv_kernel()
{
    extern __shared__ __align__(1024) char smem[];
    const uint32_t sb  = smem_u32(smem);
    const uint32_t mb0 = sb;

    const int tid  = threadIdx.x;
    const int w    = tid >> 5;
    const int lane = tid & 31;
    const int g    = lane >> 2;
    const int t    = lane & 3;
    const int b    = blockIdx.y;
    const int n0   = blockIdx.x * 128;
    const int c0   = w * 32;

    if (tid == 0) MBAR_INIT(mb0, 1);
    __syncthreads();
    if (tid == 0) {
        MBAR_EXPECT_TX(mb0, 131072);
        bulk_g2s(sb + 1024,         g_xh + ((size_t)b * NN + n0) * CH, 65536, mb0);
        bulk_g2s(sb + 1024 + 65536, g_xl + ((size_t)b * NN + n0) * CH, 65536, mb0);
    }

    float d[2][16][4];
#pragma unroll
    for (int mb = 0; mb < 2; mb++)
#pragma unroll
        for (int nb = 0; nb < 16; nb++) {
            d[mb][nb][0] = 0.f; d[mb][nb][1] = 0.f;
            d[mb][nb][2] = 0.f; d[mb][nb][3] = 0.f;
        }

    const uint32_t b_row = sb + 1024
        + (uint32_t)(((lane >> 4) * 8 + (lane & 7)) * 512);
    const int chsel = (lane >> 3) & 1;
    const int r7 = lane & 7;

    unsigned ah[2][2][4], al[2][2][4];
    load_a_frags(ah[0], al[0], g_wh, g_wl, c0, g, t, 0);

    mbar_wait(mb0, 0);
    __syncthreads();

#pragma unroll
    for (int ks = 0; ks < 16; ks++) {
        const int cur = ks & 1, nxt = cur ^ 1;
        if (ks < 15)
            load_a_frags(ah[nxt], al[nxt], g_wh, g_wl, c0, g, t, ks + 1);

        const uint32_t sw = (uint32_t)(((2 * ks + chsel) ^ r7) * 16);
#pragma unroll
        for (int p = 0; p < 8; p++) {
            uint32_t addr = b_row + (uint32_t)(p * 16 * 512) + sw;
            unsigned bh0, bh1, bh2, bh3, bl0, bl1, bl2, bl3;
            ldsm4(bh0, bh1, bh2, bh3, addr);
            ldsm4(bl0, bl1, bl2, bl3, addr + 65536);
            GEMM_P_GROUP(d, ah[cur], al[cur],
                         bh0, bh1, bh2, bh3, bl0, bl1, bl2, bl3, p);
        }
    }

    // ---- epilogue: scatter to V (warps 0-7), q (warp 8), K (warp 9) ----
    const size_t kvbase = (size_t)b * NTILES * KV_TILE_EL;
#pragma unroll
    for (int mb = 0; mb < 2; mb++) {
        int rA = c0 + mb * 16 + g;
        int rB = rA + 8;
        float biasA = g_bqkv[rA], biasB = g_bqkv[rB];
#pragma unroll
        for (int nb = 0; nb < 16; nb++) {
            int n    = n0 + nb * 8 + t * 2;
            int tile = n >> 6;
            int jt   = n & 63;
            size_t kvb = kvbase + (size_t)tile * KV_TILE_EL;
            float vA0 = d[mb][nb][0] + biasA, vA1 = d[mb][nb][1] + biasA;
            float vB0 = d[mb][nb][2] + biasB, vB1 = d[mb][nb][3] + biasB;
            if (w < 8) {
                size_t vb = kvb + 5120;
                unsigned hA = cvt_bf16x2(vA1, vA0);
                unsigned lA = cvt_bf16x2(vA1 - f_hi(hA), vA0 - f_lo(hA));
                size_t offA = (size_t)rA * 64 + (((jt >> 3) ^ (rA & 7)) << 3) + (jt & 7);
                *(unsigned*)(g_kv + vb + offA)         = hA;
                *(unsigned*)(g_kv + vb + 16384 + offA) = lA;
                unsigned hB = cvt_bf16x2(vB1, vB0);
                unsigned lB = cvt_bf16x2(vB1 - f_hi(hB), vB0 - f_lo(hB));
                size_t offB = (size_t)rB * 64 + (((jt >> 3) ^ (rB & 7)) << 3) + (jt & 7);
                *(unsigned*)(g_kv + vb + offB)         = hB;
                *(unsigned*)(g_kv + vb + 16384 + offB) = lB;
            } else if (w == 8) {
                int dA = rA - 256, dB = rB - 256;
                size_t r0 = ((size_t)b * NN + n) * CQK;
                size_t r1 = r0 + CQK;
                __nv_bfloat16 hA0 = __float2bfloat16(vA0);
                __nv_bfloat16 hA1 = __float2bfloat16(vA1);
                g_qh[r0 + dA] = hA0; g_ql[r0 + dA] = __float2bfloat16(vA0 - __bfloat162float(hA0));
                g_qh[r1 + dA] = hA1; g_ql[r1 + dA] = __float2bfloat16(vA1 - __bfloat162float(hA1));
                __nv_bfloat16 hB0 = __float2bfloat16(vB0);
                __nv_bfloat16 hB1 = __float2bfloat16(vB1);
                g_qh[r0 + dB] = hB0; g_ql[r0 + dB] = __float2bfloat16(vB0 - __bfloat162float(hB0));
                g_qh[r1 + dB] = hB1; g_ql[r1 + dB] = __float2bfloat16(vB1 - __bfloat162float(hB1));
            } else {
                int dA = rA - 288, dB = rB - 288;
                size_t k0 = kvb + (size_t)jt * KPAD;
                size_t k1 = k0 + KPAD;
                __nv_bfloat16 hA0 = __float2bfloat16(vA0);
                __nv_bfloat16 hA1 = __float2bfloat16(vA1);
                g_kv[k0 + dA] = hA0; g_kv[k0 + 2560 + dA] = __float2bfloat16(vA0 - __bfloat162float(hA0));
                g_kv[k1 + dA] = hA1; g_kv[k1 + 2560 + dA] = __float2bfloat16(vA1 - __bfloat162float(hA1));
                __nv_bfloat16 hB0 = __float2bfloat16(vB0);
                __nv_bfloat16 hB1 = __float2bfloat16(vB1);
                g_kv[k0 + dB] = hB0; g_kv[k0 + 2560 + dB] = __float2bfloat16(vB0 - __bfloat162float(hB0));
                g_kv[k1 + dB] = hB1; g_kv[k1 + 2560 + dB] = __float2bfloat16(vB1 - __bfloat162float(hB1));
            }
        }
    }
}

// ============================================================================
// Kernel 3: HMMA flash attention; per-warp kb stagger to de-phase SMSP
// co-residents; no barrier after mbar_wait.
// ============================================================================
__global__ void __launch_bounds__(256, 1)
attn_kernel()
{
    extern __shared__ __align__(1024) char smem[];

    const int tid  = threadIdx.x;
    const int w    = tid >> 5;
    const int lane = tid & 31;
    const int g    = lane >> 2;
    const int t    = lane & 3;
    const int b    = blockIdx.y;
    const int q0   = blockIdx.x * TQ;
    const int row0 = q0 + w * 16 + g;
    const int kboff = (w >> 2) << 1;      // SMSP co-residents offset by 2 kb

    const uint32_t sb  = smem_u32(smem);
    const uint32_t mb0 = sb + SM_MB0;
    const uint32_t mb1 = sb + SM_MB1;

    if (tid == 0) { MBAR_INIT(mb0, 1); MBAR_INIT(mb1, 1); }
    __syncthreads();

    const __nv_bfloat16* kv_src = g_kv + (size_t)b * NTILES * KV_TILE_EL;

    const uint32_t k_lm = (uint32_t)(((lane & 7) * KPAD + (lane >> 3) * 8) * 2);
    const int vm = lane >> 3;
    const int vr = lane & 7;
    const uint32_t v_row = (uint32_t)(((vm >> 1) * 8 + vr) * 128);

    unsigned qh[2][4], ql[2][4];
    {
        const __nv_bfloat16* qhp = g_qh + (size_t)b * NN * CQK;
        const __nv_bfloat16* qlp = g_ql + (size_t)b * NN * CQK;
#pragma unroll
        for (int kq = 0; kq < 2; kq++) {
            int c0 = kq * 16 + t * 2;
            qh[kq][0] = *(const unsigned*)(qhp + (size_t)row0 * CQK + c0);
            qh[kq][1] = *(const unsigned*)(qhp + (size_t)(row0 + 8) * CQK + c0);
            qh[kq][2] = *(const unsigned*)(qhp + (size_t)row0 * CQK + c0 + 8);
            qh[kq][3] = *(const unsigned*)(qhp + (size_t)(row0 + 8) * CQK + c0 + 8);
            ql[kq][0] = *(const unsigned*)(qlp + (size_t)row0 * CQK + c0);
            ql[kq][1] = *(const unsigned*)(qlp + (size_t)(row0 + 8) * CQK + c0);
            ql[kq][2] = *(const unsigned*)(qlp + (size_t)row0 * CQK + c0 + 8);
            ql[kq][3] = *(const unsigned*)(qlp + (size_t)(row0 + 8) * CQK + c0 + 8);
        }
    }

    float o[32][4];
#pragma unroll
    for (int cb = 0; cb < 32; cb++) {
        o[cb][0] = 0.f; o[cb][1] = 0.f; o[cb][2] = 0.f; o[cb][3] = 0.f;
    }
    float rs0 = 0.f, rs1 = 0.f;

    if (tid == 0) {
        MBAR_EXPECT_TX(mb0, KV_TILE_B);
        bulk_g2s(sb + SM_BUF, kv_src, KV_TILE_B, mb0);
    }

    for (int tl = 0; tl < NTILES; tl++) {
        if (tl + 1 < NTILES && tid == 0) {
            uint32_t mb = ((tl + 1) & 1) ? mb1 : mb0;
            MBAR_EXPECT_TX(mb, KV_TILE_B);
            bulk_g2s(sb + SM_BUF + ((tl + 1) & 1) * KV_TILE_B,
                     kv_src + (size_t)(tl + 1) * KV_TILE_EL, KV_TILE_B, mb);
        }
        mbar_wait((tl & 1) ? mb1 : mb0, (tl >> 1) & 1);

        const uint32_t bb  = sb + SM_BUF + (tl & 1) * KV_TILE_B;
        const uint32_t khb = bb + KH_OFF + k_lm;
        const uint32_t klb = bb + KL_OFF + k_lm;
        const uint32_t vhb = bb + V_OFF + v_row;
        const uint32_t vlb = vhb + 32768;

#pragma unroll
        for (int kb = 0; kb < 4; kb++) {
            const int kbx = (kb + kboff) & 3;     // staggered kb order
            const uint32_t vsw = (uint32_t)(((kbx * 2 + (vm & 1)) ^ vr) * 16);

            float s0a[4] = {0.f, 0.f, 0.f, 0.f};
            float s0b[4] = {0.f, 0.f, 0.f, 0.f};
            float s1a[4] = {0.f, 0.f, 0.f, 0.f};
            float s1b[4] = {0.f, 0.f, 0.f, 0.f};
#pragma unroll
            for (int jbi = 0; jbi < 2; jbi++) {
                const uint32_t koff = (uint32_t)((kbx * 2 + jbi) * 8 * KPAD * 2);
                unsigned kh0, kh1, kh2, kh3, kl0, kl1, kl2, kl3;
                ldsm4(kh0, kh1, kh2, kh3, khb + koff);
                ldsm4(kl0, kl1, kl2, kl3, klb + koff);
                float* sa = jbi ? s1a : s0a;
                float* sc = jbi ? s1b : s0b;
                mma_bf16(sa, qh[0], kh0, kh1);
                mma_bf16(sc, qh[1], kh2, kh3);
                mma_bf16(sa, qh[0], kl0, kl1);
                mma_bf16(sc, qh[1], kl2, kl3);
                mma_bf16(sa, ql[0], kh0, kh1);
                mma_bf16(sc, ql[1], kh2, kh3);
            }

            float e00 = __expf(s0a[0] + s0b[0]), e01 = __expf(s0a[1] + s0b[1]);
            float e02 = __expf(s0a[2] + s0b[2]), e03 = __expf(s0a[3] + s0b[3]);
            float e10 = __expf(s1a[0] + s1b[0]), e11 = __expf(s1a[1] + s1b[1]);
            float e12 = __expf(s1a[2] + s1b[2]), e13 = __expf(s1a[3] + s1b[3]);
            rs0 += e00 + e01 + e10 + e11;
            rs1 += e02 + e03 + e12 + e13;

            unsigned pa[4], pl[4];
            pa[0] = cvt_bf16x2(e01, e00);
            pa[1] = cvt_bf16x2(e03, e02);
            pa[2] = cvt_bf16x2(e11, e10);
            pa[3] = cvt_bf16x2(e13, e12);
            pl[0] = cvt_bf16x2(e01 - f_hi(pa[0]), e00 - f_lo(pa[0]));
            pl[1] = cvt_bf16x2(e03 - f_hi(pa[1]), e02 - f_lo(pa[1]));
            pl[2] = cvt_bf16x2(e11 - f_hi(pa[2]), e10 - f_lo(pa[2]));
            pl[3] = cvt_bf16x2(e13 - f_hi(pa[3]), e12 - f_lo(pa[3]));

            uint32_t avh = vhb + vsw;
            uint32_t avl = vlb + vsw;
#pragma unroll
            for (int p = 0; p < 16; p++) {
                unsigned vh0a, vh1a, vh0b, vh1b;
                unsigned vl0a, vl1a, vl0b, vl1b;
                ldsm4(vh0a, vh1a, vh0b, vh1b, avh);
                ldsm4(vl0a, vl1a, vl0b, vl1b, avl);
                mma_bf16(o[2 * p],     pa, vh0a, vh1a);
                mma_bf16(o[2 * p + 1], pa, vh0b, vh1b);
                mma_bf16(o[2 * p],     pa, vl0a, vl1a);
                mma_bf16(o[2 * p + 1], pa, vl0b, vl1b);
                mma_bf16(o[2 * p],     pl, vh0a, vh1a);
                mma_bf16(o[2 * p + 1], pl, vh0b, vh1b);
                avh += 16 * 128;
                avl += 16 * 128;
            }
        }
        __syncthreads();   // buffer reuse safety (next-next bulk overwrite)
    }

    rs0 += __shfl_xor_sync(0xffffffffu, rs0, 1);
    rs0 += __shfl_xor_sync(0xffffffffu, rs0, 2);
    rs1 += __shfl_xor_sync(0xffffffffu, rs1, 1);
    rs1 += __shfl_xor_sync(0xffffffffu, rs1, 2);
    const float inv0 = 1.0f / rs0;
    const float inv1 = 1.0f / rs1;

    const size_t r0b = ((size_t)b * NN + row0) * CH;
    const size_t r1b = ((size_t)b * NN + row0 + 8) * CH;
#pragma unroll
    for (int cb = 0; cb < 32; cb++) {
        size_t off = (size_t)(((cb ^ g) << 3) + t * 2);
        float v0 = o[cb][0] * inv0, v1 = o[cb][1] * inv0;
        unsigned h = cvt_bf16x2(v1, v0);
        unsigned l = cvt_bf16x2(v1 - f_hi(h), v0 - f_lo(h));
        *(unsigned*)(g_aoh + r0b + off) = h;
        *(unsigned*)(g_aol + r0b + off) = l;
        float u0 = o[cb][2] * inv1, u1 = o[cb][3] * inv1;
        unsigned h2 = cvt_bf16x2(u1, u0);
        unsigned l2 = cvt_bf16x2(u1 - f_hi(h2), u0 - f_lo(h2));
        *(unsigned*)(g_aoh + r1b + off) = h2;
        *(unsigned*)(g_aol + r1b + off) = l2;
    }
}

// ============================================================================
// Kernel 4: HMMA output projection + residual (unchanged from R11)
// ============================================================================
__global__ void __launch_bounds__(256, 1)
final_kernel(const float* __restrict__ x,
             const float* __restrict__ bg,
             float* __restrict__ y)
{
    extern __shared__ __align__(1024) char smem[];
    const uint32_t sb  = smem_u32(smem);
    const uint32_t mb0 = sb;

    const int tid  = threadIdx.x;
    const int w    = tid >> 5;
    const int lane = tid & 31;
    const int g    = lane >> 2;
    const int t    = lane & 3;
    const int b    = blockIdx.y;
    const int n0   = blockIdx.x * 128;
    const int c0   = w * 32;

    if (tid == 0) MBAR_INIT(mb0, 1);
    __syncthreads();
    if (tid == 0) {
        MBAR_EXPECT_TX(mb0, 131072);
        bulk_g2s(sb + 1024,         g_aoh + ((size_t)b * NN + n0) * CH, 65536, mb0);
        bulk_g2s(sb + 1024 + 65536, g_aol + ((size_t)b * NN + n0) * CH, 65536, mb0);
    }

    float d[2][16][4];
#pragma unroll
    for (int mb = 0; mb < 2; mb++)
#pragma unroll
        for (int nb = 0; nb < 16; nb++) {
            d[mb][nb][0] = 0.f; d[mb][nb][1] = 0.f;
            d[mb][nb][2] = 0.f; d[mb][nb][3] = 0.f;
        }

    const uint32_t ao_row = sb + 1024
        + (uint32_t)(((lane >> 4) * 8 + (lane & 7)) * 512);
    const int chsel = (lane >> 3) & 1;
    const int r7 = lane & 7;

    unsigned ah[2][2][4], al[2][2][4];
    load_a_frags(ah[0], al[0], g_wgh, g_wgl, c0, g, t, 0);

    mbar_wait(mb0, 0);
    __syncthreads();

#pragma unroll
    for (int ks = 0; ks < 16; ks++) {
        const int cur = ks & 1, nxt = cur ^ 1;
        if (ks < 15)
            load_a_frags(ah[nxt], al[nxt], g_wgh, g_wgl, c0, g, t, ks + 1);

        const uint32_t sw = (uint32_t)((((2 * ks + chsel) ^ r7)) * 16);
#pragma unroll
        for (int p = 0; p < 8; p++) {
            uint32_t addr = ao_row + (uint32_t)(p * 16 * 512) + sw;
            unsigned bh0, bh1, bh2, bh3, bl0, bl1, bl2, bl3;
            ldsm4(bh0, bh1, bh2, bh3, addr);
            ldsm4(bl0, bl1, bl2, bl3, addr + 65536);
            GEMM_P_GROUP(d, ah[cur], al[cur],
                         bh0, bh1, bh2, bh3, bl0, bl1, bl2, bl3, p);
        }
    }

#pragma unroll
    for (int mb = 0; mb < 2; mb++) {
        int cA = c0 + mb * 16 + g;
        int cB = cA + 8;
        float bgA = bg[cA], bgB = bg[cB];
        const float* xA = x + ((size_t)b * CH + cA) * NN + n0 + t * 2;
        const float* xB = x + ((size_t)b * CH + cB) * NN + n0 + t * 2;
        float* yA = y + ((size_t)b * CH + cA) * NN + n0 + t * 2;
        float* yB = y + ((size_t)b * CH + cB) * NN + n0 + t * 2;
#pragma unroll
        for (int nb = 0; nb < 16; nb++) {
            float2 xr = *(const float2*)(xA + nb * 8);
            *(float2*)(yA + nb * 8) =
                make_float2(xr.x + bgA + d[mb][nb][0],
                            xr.y + bgA + d[mb][nb][1]);
            float2 xs2 = *(const float2*)(xB + nb * 8);
            *(float2*)(yB + nb * 8) =
                make_float2(xs2.x + bgB + d[mb][nb][2],
                            xs2.y + bgB + d[mb][nb][3]);
        }
    }
}

// ============================================================================
extern "C" void kernel_launch(void* const* d_in, const int* in_sizes, int n_in,
                              void* d_out, int out_size)
{
    const float* x  = (const float*)d_in[0];
    const float* wq = (const float*)d_in[1];
    const float* bq = (const float*)d_in[2];
    const float* wk = (const float*)d_in[3];
    const float* bk = (const float*)d_in[4];
    const float* wv = (const float*)d_in[5];
    const float* bv = (const float*)d_in[6];
    const float* wg = (const float*)d_in[7];
    const float* bg = (const float*)d_in[8];
    float* y = (float*)d_out;

    cudaFuncSetAttribute(attn_kernel,
                         cudaFuncAttributeMaxDynamicSharedMemorySize, SM_TOTAL);
    cudaFuncSetAttribute(qkv_kernel,
                         cudaFuncAttributeMaxDynamicSharedMemorySize, GEMM_SM_TOTAL);
    cudaFuncSetAttribute(final_kernel,
                         cudaFuncAttributeMaxDynamicSharedMemorySize, GEMM_SM_TOTAL);

    wgprep_kernel  <<<CH * CH / 512, 256>>>(wg);
    wqkvprep_kernel<<<320 * CH / 512, 256>>>(wv, bv, wq, bq, wk, bk);
    xprep_kernel   <<<dim3(NN / 32, BATCH), 256>>>(x);
    qkv_kernel     <<<dim3(NN / 128, BATCH), 320, GEMM_SM_TOTAL>>>();
    attn_kernel    <<<dim3(NN / TQ, BATCH), 256, SM_TOTAL>>>();
    final_kernel   <<<dim3(NN / 128, BATCH), 256, GEMM_SM_TOTAL>>>(x, bg, y);
}

// round 14
// speedup vs baseline: 1.6034x; 1.6034x over previous
#include <cuda_runtime.h>
#include <cuda_bf16.h>
#include <cstdint>

#define BATCH 4
#define CH    256
#define CQK   32
#define NN    4096

#define TQ     128
#define TJ     64
#define NTILES (NN / TJ)   // 64

// ---- unified KV tile: [KH 64x40 bf16][KL 64x40 bf16][V 256x64 fp16]
#define KPAD       40
#define KV_TILE_EL 21504                  // 2-byte elements
#define KV_TILE_B  43008
#define KH_OFF     0                      // bytes
#define KL_OFF     5120
#define V_OFF      10240
#define SM_MB0  0
#define SM_MB1  8
#define SM_BUF  1024
#define SM_TOTAL (SM_BUF + 2 * KV_TILE_B)   // 87040

// rowmax kernel SMEM: [mbar pad 1024][2 x KH 5120]
#define RM_SM_TOTAL (1024 + 2 * 5120)

// GEMM kernels SMEM: [mbar pad 1024][B_hi 64KB][B_lo 64KB]
#define GEMM_SM_TOTAL (1024 + 2 * 65536)

// ---------------- scratch (device globals; no allocation allowed) ----------
__device__ __nv_bfloat16 g_qh[(size_t)BATCH * NN * CQK];
__device__ __nv_bfloat16 g_ql[(size_t)BATCH * NN * CQK];
__device__ __align__(128) __nv_bfloat16 g_kv[(size_t)BATCH * NTILES * KV_TILE_EL];
__device__ __align__(128) __nv_bfloat16 g_aoh[(size_t)BATCH * NN * CH];  // swizzled
__device__ __align__(128) __nv_bfloat16 g_aol[(size_t)BATCH * NN * CH];
__device__ __align__(128) __nv_bfloat16 g_xh[(size_t)BATCH * NN * CH];   // x^T swizzled
__device__ __align__(128) __nv_bfloat16 g_xl[(size_t)BATCH * NN * CH];
__device__ __nv_bfloat16 g_wgh[CH * CH];
__device__ __nv_bfloat16 g_wgl[CH * CH];
__device__ __nv_bfloat16 g_wh[320 * CH];   // [wv;wq;wk] hi
__device__ __nv_bfloat16 g_wl[320 * CH];
__device__ float         g_bqkv[320];
__device__ float         g_rmax[(size_t)BATCH * NN];

// ---------------- helpers ---------------------------------------------------
__device__ __forceinline__ unsigned cvt_bf16x2(float hi, float lo) {
    unsigned r;
    asm("cvt.rn.bf16x2.f32 %0, %1, %2;" : "=r"(r) : "f"(hi), "f"(lo));
    return r;
}
__device__ __forceinline__ unsigned cvt_f16x2(float hi, float lo) {
    unsigned r;
    asm("cvt.rn.f16x2.f32 %0, %1, %2;" : "=r"(r) : "f"(hi), "f"(lo));
    return r;
}
__device__ __forceinline__ float f_lo(unsigned u) { return __uint_as_float(u << 16); }
__device__ __forceinline__ float f_hi(unsigned u) { return __uint_as_float(u & 0xffff0000u); }

__device__ __forceinline__ uint32_t smem_u32(const void* p) {
    uint32_t a;
    asm("{ .reg .u64 t; cvta.to.shared.u64 t, %1; cvt.u32.u64 %0, t; }"
        : "=r"(a) : "l"(p));
    return a;
}

#define MBAR_INIT(addr, cnt) \
    asm volatile("mbarrier.init.shared.b64 [%0], %1;" :: "r"(addr), "r"(cnt) : "memory")
#define MBAR_EXPECT_TX(addr, bytes) \
    asm volatile("mbarrier.arrive.expect_tx.shared.b64 _, [%0], %1;" \
                 :: "r"(addr), "r"(bytes) : "memory")

__device__ __forceinline__ void mbar_wait(uint32_t addr, uint32_t parity) {
    asm volatile(
        "{\n\t.reg .pred P;\n\t"
        "WL_%=:\n\t"
        "mbarrier.try_wait.parity.acquire.cta.shared::cta.b64 P, [%0], %1, 0x989680;\n\t"
        "@P bra WD_%=;\n\t"
        "bra WL_%=;\n\t"
        "WD_%=:\n\t}"
        :: "r"(addr), "r"(parity) : "memory");
}
__device__ __forceinline__ void bulk_g2s(uint32_t dst, const void* src,
                                         uint32_t bytes, uint32_t mbar) {
    asm volatile(
        "cp.async.bulk.shared::cluster.global.mbarrier::complete_tx::bytes "
        "[%0], [%1], %2, [%3];"
        :: "r"(dst), "l"(src), "r"(bytes), "r"(mbar) : "memory");
}

__device__ __forceinline__ void ldsm4(unsigned& r0, unsigned& r1,
                                      unsigned& r2, unsigned& r3, uint32_t a) {
    asm volatile("ldmatrix.sync.aligned.m8n8.x4.shared.b16 {%0,%1,%2,%3}, [%4];"
                 : "=r"(r0), "=r"(r1), "=r"(r2), "=r"(r3) : "r"(a));
}

__device__ __forceinline__ void mma_bf16(float* d, const unsigned* a,
                                         unsigned b0, unsigned b1) {
    asm volatile(
        "mma.sync.aligned.m16n8k16.row.col.f32.bf16.bf16.f32 "
        "{%0,%1,%2,%3}, {%4,%5,%6,%7}, {%8,%9}, {%0,%1,%2,%3};"
        : "+f"(d[0]), "+f"(d[1]), "+f"(d[2]), "+f"(d[3])
        : "r"(a[0]), "r"(a[1]), "r"(a[2]), "r"(a[3]), "r"(b0), "r"(b1));
}
__device__ __forceinline__ void mma_f16(float* d, const unsigned* a,
                                        unsigned b0, unsigned b1) {
    asm volatile(
        "mma.sync.aligned.m16n8k16.row.col.f32.f16.f16.f32 "
        "{%0,%1,%2,%3}, {%4,%5,%6,%7}, {%8,%9}, {%0,%1,%2,%3};"
        : "+f"(d[0]), "+f"(d[1]), "+f"(d[2]), "+f"(d[3])
        : "r"(a[0]), "r"(a[1]), "r"(a[2]), "r"(a[3]), "r"(b0), "r"(b1));
}

// load A fragments (weights) for k-slice ks
__device__ __forceinline__ void load_a_frags(
    unsigned ah[2][4], unsigned al[2][4],
    const __nv_bfloat16* wh, const __nv_bfloat16* wl,
    int c0, int g, int t, int ks)
{
#pragma unroll
    for (int mb = 0; mb < 2; mb++) {
        int cr  = c0 + mb * 16 + g;
        int col = ks * 16 + t * 2;
        ah[mb][0] = *(const unsigned*)(wh + cr * CH + col);
        ah[mb][1] = *(const unsigned*)(wh + (cr + 8) * CH + col);
        ah[mb][2] = *(const unsigned*)(wh + cr * CH + col + 8);
        ah[mb][3] = *(const unsigned*)(wh + (cr + 8) * CH + col + 8);
        al[mb][0] = *(const unsigned*)(wl + cr * CH + col);
        al[mb][1] = *(const unsigned*)(wl + (cr + 8) * CH + col);
        al[mb][2] = *(const unsigned*)(wl + cr * CH + col + 8);
        al[mb][3] = *(const unsigned*)(wl + (cr + 8) * CH + col + 8);
    }
}

// 12 MMAs for one p-group
#define GEMM_P_GROUP(d, ah, al, bh0, bh1, bh2, bh3, bl0, bl1, bl2, bl3, p) \
    do {                                                                   \
        mma_bf16(d[0][2*(p)],     ah[0], bh0, bh1);                        \
        mma_bf16(d[0][2*(p) + 1], ah[0], bh2, bh3);                        \
        mma_bf16(d[1][2*(p)],     ah[1], bh0, bh1);                        \
        mma_bf16(d[1][2*(p) + 1], ah[1], bh2, bh3);                        \
        mma_bf16(d[0][2*(p)],     ah[0], bl0, bl1);                        \
        mma_bf16(d[0][2*(p) + 1], ah[0], bl2, bl3);                        \
        mma_bf16(d[1][2*(p)],     ah[1], bl0, bl1);                        \
        mma_bf16(d[1][2*(p) + 1], ah[1], bl2, bl3);                        \
        mma_bf16(d[0][2*(p)],     al[0], bh0, bh1);                        \
        mma_bf16(d[0][2*(p) + 1], al[0], bh2, bh3);                        \
        mma_bf16(d[1][2*(p)],     al[1], bh0, bh1);                        \
        mma_bf16(d[1][2*(p) + 1], al[1], bh2, bh3);                        \
    } while (0)

// ============================================================================
// Kernel P0: wg -> bf16 hi/lo
// ============================================================================
__global__ void __launch_bounds__(256)
wgprep_kernel(const float* __restrict__ wg)
{
    int i = blockIdx.x * 256 + threadIdx.x;
    float a = wg[2 * i], b = wg[2 * i + 1];
    unsigned h = cvt_bf16x2(b, a);
    unsigned l = cvt_bf16x2(b - f_hi(h), a - f_lo(h));
    *(unsigned*)(g_wgh + 2 * i) = h;
    *(unsigned*)(g_wgl + 2 * i) = l;
}

// ============================================================================
// Kernel P1: stacked [wv;wq;wk] -> bf16 hi/lo + combined bias
// ============================================================================
__global__ void __launch_bounds__(256)
wqkvprep_kernel(const float* __restrict__ wv, const float* __restrict__ bv,
                const float* __restrict__ wq, const float* __restrict__ bq,
                const float* __restrict__ wk, const float* __restrict__ bk)
{
    int i = blockIdx.x * 256 + threadIdx.x;
    int row  = i >> 7;
    int col2 = (i & 127) * 2;
    const float* src = (row < 256) ? wv + row * CH
                     : (row < 288) ? wq + (row - 256) * CH
                                   : wk + (row - 288) * CH;
    float a = src[col2], b = src[col2 + 1];
    unsigned h = cvt_bf16x2(b, a);
    unsigned l = cvt_bf16x2(b - f_hi(h), a - f_lo(h));
    *(unsigned*)(g_wh + row * CH + col2) = h;
    *(unsigned*)(g_wl + row * CH + col2) = l;
    if (i < 320)
        g_bqkv[i] = (i < 256) ? bv[i] : (i < 288) ? bq[i - 256] : bk[i - 288];
}

// ============================================================================
// Kernel P2: x [b][c][n] fp32 -> x^T [b][n][c] bf16 hi/lo, ldmatrix-swizzled
// ============================================================================
__global__ void __launch_bounds__(256)
xprep_kernel(const float* __restrict__ x)
{
    __shared__ __align__(16) float xs[CH * 33];
    const int b   = blockIdx.y;
    const int n0  = blockIdx.x * 32;
    const int tid = threadIdx.x;

    const float* xb = x + (size_t)b * CH * NN + n0;
    for (int idx = tid; idx < CH * 32; idx += 256) {
        int c = idx >> 5, n = idx & 31;
        xs[c * 33 + n] = xb[(size_t)c * NN + n];
    }
    __syncthreads();

    const int n   = tid & 31;
    const int g3  = tid >> 5;
    const int nsw = (n0 + n) & 7;
    __nv_bfloat16* dh = g_xh + ((size_t)b * NN + n0 + n) * CH;
    __nv_bfloat16* dl = g_xl + ((size_t)b * NN + n0 + n) * CH;

#pragma unroll
    for (int cc = 0; cc < 4; cc++) {
        int ch = g3 * 4 + cc;
        float v[8];
#pragma unroll
        for (int j = 0; j < 8; j++) v[j] = xs[(ch * 8 + j) * 33 + n];
        unsigned h[4], l[4];
#pragma unroll
        for (int j = 0; j < 4; j++) {
            h[j] = cvt_bf16x2(v[2 * j + 1], v[2 * j]);
            l[j] = cvt_bf16x2(v[2 * j + 1] - f_hi(h[j]), v[2 * j] - f_lo(h[j]));
        }
        int mch = (ch ^ nsw) << 3;
        *(uint4*)(dh + mch) = make_uint4(h[0], h[1], h[2], h[3]);
        *(uint4*)(dl + mch) = make_uint4(l[0], l[1], l[2], l[3]);
    }
}

// ============================================================================
// Kernel P3: fused q/k/v projection via HMMA; V stored as fp16 single.
// ============================================================================
__global__ void __launch_bounds__(320, 1)
qkv_kernel()
{
    extern __shared__ __align__(1024) char smem[];
    const uint32_t sb  = smem_u32(smem);
    const uint32_t mb0 = sb;

    const int tid  = threadIdx.x;
    const int w    = tid >> 5;
    const int lane = tid & 31;
    const int g    = lane >> 2;
    const int t    = lane & 3;
    const int b    = blockIdx.y;
    const int n0   = blockIdx.x * 128;
    const int c0   = w * 32;

    if (tid == 0) MBAR_INIT(mb0, 1);
    __syncthreads();
    if (tid == 0) {
        MBAR_EXPECT_TX(mb0, 131072);
        bulk_g2s(sb + 1024,         g_xh + ((size_t)b * NN + n0) * CH, 65536, mb0);
        bulk_g2s(sb + 1024 + 65536, g_xl + ((size_t)b * NN + n0) * CH, 65536, mb0);
    }

    float d[2][16][4];
#pragma unroll
    for (int mb = 0; mb < 2; mb++)
#pragma unroll
        for (int nb = 0; nb < 16; nb++) {
            d[mb][nb][0] = 0.f; d[mb][nb][1] = 0.f;
            d[mb][nb][2] = 0.f; d[mb][nb][3] = 0.f;
        }

    const uint32_t b_row = sb + 1024
        + (uint32_t)(((lane >> 4) * 8 + (lane & 7)) * 512);
    const int chsel = (lane >> 3) & 1;
    const int r7 = lane & 7;

    unsigned ah[2][2][4], al[2][2][4];
    load_a_frags(ah[0], al[0], g_wh, g_wl, c0, g, t, 0);

    mbar_wait(mb0, 0);
    __syncthreads();

#pragma unroll
    for (int ks = 0; ks < 16; ks++) {
        const int cur = ks & 1, nxt = cur ^ 1;
        if (ks < 15)
            load_a_frags(ah[nxt], al[nxt], g_wh, g_wl, c0, g, t, ks + 1);

        const uint32_t sw = (uint32_t)(((2 * ks + chsel) ^ r7) * 16);
#pragma unroll
        for (int p = 0; p < 8; p++) {
            uint32_t addr = b_row + (uint32_t)(p * 16 * 512) + sw;
            unsigned bh0, bh1, bh2, bh3, bl0, bl1, bl2, bl3;
            ldsm4(bh0, bh1, bh2, bh3, addr);
            ldsm4(bl0, bl1, bl2, bl3, addr + 65536);
            GEMM_P_GROUP(d, ah[cur], al[cur],
                         bh0, bh1, bh2, bh3, bl0, bl1, bl2, bl3, p);
        }
    }

    // ---- epilogue: scatter to V fp16 (warps 0-7), q (warp 8), K (warp 9) ----
    const size_t kvbase = (size_t)b * NTILES * KV_TILE_EL;
#pragma unroll
    for (int mb = 0; mb < 2; mb++) {
        int rA = c0 + mb * 16 + g;
        int rB = rA + 8;
        float biasA = g_bqkv[rA], biasB = g_bqkv[rB];
#pragma unroll
        for (int nb = 0; nb < 16; nb++) {
            int n    = n0 + nb * 8 + t * 2;
            int tile = n >> 6;
            int jt   = n & 63;
            size_t kvb = kvbase + (size_t)tile * KV_TILE_EL;
            float vA0 = d[mb][nb][0] + biasA, vA1 = d[mb][nb][1] + biasA;
            float vB0 = d[mb][nb][2] + biasB, vB1 = d[mb][nb][3] + biasB;
            if (w < 8) {
                size_t vb = kvb + 5120;   // V region (element offset)
                size_t offA = (size_t)rA * 64 + (((jt >> 3) ^ (rA & 7)) << 3) + (jt & 7);
                *(unsigned*)(g_kv + vb + offA) = cvt_f16x2(vA1, vA0);
                size_t offB = (size_t)rB * 64 + (((jt >> 3) ^ (rB & 7)) << 3) + (jt & 7);
                *(unsigned*)(g_kv + vb + offB) = cvt_f16x2(vB1, vB0);
            } else if (w == 8) {
                int dA = rA - 256, dB = rB - 256;
                size_t r0 = ((size_t)b * NN + n) * CQK;
                size_t r1 = r0 + CQK;
                __nv_bfloat16 hA0 = __float2bfloat16(vA0);
                __nv_bfloat16 hA1 = __float2bfloat16(vA1);
                g_qh[r0 + dA] = hA0; g_ql[r0 + dA] = __float2bfloat16(vA0 - __bfloat162float(hA0));
                g_qh[r1 + dA] = hA1; g_ql[r1 + dA] = __float2bfloat16(vA1 - __bfloat162float(hA1));
                __nv_bfloat16 hB0 = __float2bfloat16(vB0);
                __nv_bfloat16 hB1 = __float2bfloat16(vB1);
                g_qh[r0 + dB] = hB0; g_ql[r0 + dB] = __float2bfloat16(vB0 - __bfloat162float(hB0));
                g_qh[r1 + dB] = hB1; g_ql[r1 + dB] = __float2bfloat16(vB1 - __bfloat162float(hB1));
            } else {
                int dA = rA - 288, dB = rB - 288;
                size_t k0 = kvb + (size_t)jt * KPAD;
                size_t k1 = k0 + KPAD;
                __nv_bfloat16 hA0 = __float2bfloat16(vA0);
                __nv_bfloat16 hA1 = __float2bfloat16(vA1);
                g_kv[k0 + dA] = hA0; g_kv[k0 + 2560 + dA] = __float2bfloat16(vA0 - __bfloat162float(hA0));
                g_kv[k1 + dA] = hA1; g_kv[k1 + 2560 + dA] = __float2bfloat16(vA1 - __bfloat162float(hA1));
                __nv_bfloat16 hB0 = __float2bfloat16(vB0);
                __nv_bfloat16 hB1 = __float2bfloat16(vB1);
                g_kv[k0 + dB] = hB0; g_kv[k0 + 2560 + dB] = __float2bfloat16(vB0 - __bfloat162float(hB0));
                g_kv[k1 + dB] = hB1; g_kv[k1 + 2560 + dB] = __float2bfloat16(vB1 - __bfloat162float(hB1));
            }
        }
    }
}

// ============================================================================
// Kernel P4: row max of energies (1-pass bf16 QK). Writes g_rmax[b][n].
// ============================================================================
__global__ void __launch_bounds__(256, 1)
rowmax_kernel()
{
    extern __shared__ __align__(1024) char smem[];
    const uint32_t sb  = smem_u32(smem);
    const uint32_t mb0 = sb + SM_MB0;
    const uint32_t mb1 = sb + SM_MB1;

    const int tid  = threadIdx.x;
    const int w    = tid >> 5;
    const int lane = tid & 31;
    const int g    = lane >> 2;
    const int t    = lane & 3;
    const int b    = blockIdx.y;
    const int q0   = blockIdx.x * TQ;
    const int row0 = q0 + w * 16 + g;

    if (tid == 0) { MBAR_INIT(mb0, 1); MBAR_INIT(mb1, 1); }
    __syncthreads();

    const __nv_bfloat16* kv_src = g_kv + (size_t)b * NTILES * KV_TILE_EL;
    const uint32_t k_lm = (uint32_t)(((lane & 7) * KPAD + (lane >> 3) * 8) * 2);

    unsigned qh[2][4];
    {
        const __nv_bfloat16* qhp = g_qh + (size_t)b * NN * CQK;
#pragma unroll
        for (int kq = 0; kq < 2; kq++) {
            int c0 = kq * 16 + t * 2;
            qh[kq][0] = *(const unsigned*)(qhp + (size_t)row0 * CQK + c0);
            qh[kq][1] = *(const unsigned*)(qhp + (size_t)(row0 + 8) * CQK + c0);
            qh[kq][2] = *(const unsigned*)(qhp + (size_t)row0 * CQK + c0 + 8);
            qh[kq][3] = *(const unsigned*)(qhp + (size_t)(row0 + 8) * CQK + c0 + 8);
        }
    }

    float m0 = -1e30f, m1 = -1e30f;

    if (tid == 0) {
        MBAR_EXPECT_TX(mb0, 5120);
        bulk_g2s(sb + SM_BUF, kv_src, 5120, mb0);
    }

    for (int tl = 0; tl < NTILES; tl++) {
        if (tl + 1 < NTILES && tid == 0) {
            uint32_t mb = ((tl + 1) & 1) ? mb1 : mb0;
            MBAR_EXPECT_TX(mb, 5120);
            bulk_g2s(sb + SM_BUF + ((tl + 1) & 1) * 5120,
                     kv_src + (size_t)(tl + 1) * KV_TILE_EL, 5120, mb);
        }
        mbar_wait((tl & 1) ? mb1 : mb0, (tl >> 1) & 1);

        const uint32_t khb = sb + SM_BUF + (tl & 1) * 5120 + k_lm;

#pragma unroll
        for (int jb = 0; jb < 8; jb++) {
            unsigned kh0, kh1, kh2, kh3;
            ldsm4(kh0, kh1, kh2, kh3, khb + (uint32_t)(jb * 8 * KPAD * 2));
            float sA[4] = {0.f, 0.f, 0.f, 0.f};
            float sB[4] = {0.f, 0.f, 0.f, 0.f};
            mma_bf16(sA, qh[0], kh0, kh1);
            mma_bf16(sB, qh[1], kh2, kh3);
            m0 = fmaxf(m0, fmaxf(sA[0] + sB[0], sA[1] + sB[1]));
            m1 = fmaxf(m1, fmaxf(sA[2] + sB[2], sA[3] + sB[3]));
        }
        __syncthreads();
    }

    m0 = fmaxf(m0, __shfl_xor_sync(0xffffffffu, m0, 1));
    m0 = fmaxf(m0, __shfl_xor_sync(0xffffffffu, m0, 2));
    m1 = fmaxf(m1, __shfl_xor_sync(0xffffffffu, m1, 1));
    m1 = fmaxf(m1, __shfl_xor_sync(0xffffffffu, m1, 2));
    if (t == 0) {
        g_rmax[(size_t)b * NN + row0]     = m0;
        g_rmax[(size_t)b * NN + row0 + 8] = m1;
    }
}

// ============================================================================
// Kernel 3: HMMA flash attention; QK 3-pass bf16, PV 1-pass fp16 (max-sub).
// ============================================================================
__global__ void __launch_bounds__(256, 1)
attn_kernel()
{
    extern __shared__ __align__(1024) char smem[];

    const int tid  = threadIdx.x;
    const int w    = tid >> 5;
    const int lane = tid & 31;
    const int g    = lane >> 2;
    const int t    = lane & 3;
    const int b    = blockIdx.y;
    const int q0   = blockIdx.x * TQ;
    const int row0 = q0 + w * 16 + g;

    const uint32_t sb  = smem_u32(smem);
    const uint32_t mb0 = sb + SM_MB0;
    const uint32_t mb1 = sb + SM_MB1;

    if (tid == 0) { MBAR_INIT(mb0, 1); MBAR_INIT(mb1, 1); }
    __syncthreads();

    const __nv_bfloat16* kv_src = g_kv + (size_t)b * NTILES * KV_TILE_EL;

    const uint32_t k_lm = (uint32_t)(((lane & 7) * KPAD + (lane >> 3) * 8) * 2);
    const int vm = lane >> 3;
    const int vr = lane & 7;
    const uint32_t v_row = (uint32_t)(((vm >> 1) * 8 + vr) * 128);  // 128 B/row

    const float gm0 = g_rmax[(size_t)b * NN + row0];
    const float gm1 = g_rmax[(size_t)b * NN + row0 + 8];

    unsigned qh[2][4], ql[2][4];
    {
        const __nv_bfloat16* qhp = g_qh + (size_t)b * NN * CQK;
        const __nv_bfloat16* qlp = g_ql + (size_t)b * NN * CQK;
#pragma unroll
        for (int kq = 0; kq < 2; kq++) {
            int c0 = kq * 16 + t * 2;
            qh[kq][0] = *(const unsigned*)(qhp + (size_t)row0 * CQK + c0);
            qh[kq][1] = *(const unsigned*)(qhp + (size_t)(row0 + 8) * CQK + c0);
            qh[kq][2] = *(const unsigned*)(qhp + (size_t)row0 * CQK + c0 + 8);
            qh[kq][3] = *(const unsigned*)(qhp + (size_t)(row0 + 8) * CQK + c0 + 8);
            ql[kq][0] = *(const unsigned*)(qlp + (size_t)row0 * CQK + c0);
            ql[kq][1] = *(const unsigned*)(qlp + (size_t)(row0 + 8) * CQK + c0);
            ql[kq][2] = *(const unsigned*)(qlp + (size_t)row0 * CQK + c0 + 8);
            ql[kq][3] = *(const unsigned*)(qlp + (size_t)(row0 + 8) * CQK + c0 + 8);
        }
    }

    float o[32][4];
#pragma unroll
    for (int cb = 0; cb < 32; cb++) {
        o[cb][0] = 0.f; o[cb][1] = 0.f; o[cb][2] = 0.f; o[cb][3] = 0.f;
    }
    float rs0 = 0.f, rs1 = 0.f;

    if (tid == 0) {
        MBAR_EXPECT_TX(mb0, KV_TILE_B);
        bulk_g2s(sb + SM_BUF, kv_src, KV_TILE_B, mb0);
    }

    for (int tl = 0; tl < NTILES; tl++) {
        if (tl + 1 < NTILES && tid == 0) {
            uint32_t mb = ((tl + 1) & 1) ? mb1 : mb0;
            MBAR_EXPECT_TX(mb, KV_TILE_B);
            bulk_g2s(sb + SM_BUF + ((tl + 1) & 1) * KV_TILE_B,
                     kv_src + (size_t)(tl + 1) * KV_TILE_EL, KV_TILE_B, mb);
        }
        mbar_wait((tl & 1) ? mb1 : mb0, (tl >> 1) & 1);
        __syncthreads();

        const uint32_t bb  = sb + SM_BUF + (tl & 1) * KV_TILE_B;
        const uint32_t khb = bb + KH_OFF + k_lm;
        const uint32_t klb = bb + KL_OFF + k_lm;
        const uint32_t vhb = bb + V_OFF + v_row;

#pragma unroll
        for (int kb = 0; kb < 4; kb++) {
            const uint32_t vsw = (uint32_t)(((kb * 2 + (vm & 1)) ^ vr) * 16);

            float s0a[4] = {0.f, 0.f, 0.f, 0.f};
            float s0b[4] = {0.f, 0.f, 0.f, 0.f};
            float s1a[4] = {0.f, 0.f, 0.f, 0.f};
            float s1b[4] = {0.f, 0.f, 0.f, 0.f};
#pragma unroll
            for (int jbi = 0; jbi < 2; jbi++) {
                const uint32_t koff = (uint32_t)((kb * 2 + jbi) * 8 * KPAD * 2);
                unsigned kh0, kh1, kh2, kh3, kl0, kl1, kl2, kl3;
                ldsm4(kh0, kh1, kh2, kh3, khb + koff);
                ldsm4(kl0, kl1, kl2, kl3, klb + koff);
                float* sa = jbi ? s1a : s0a;
                float* sc = jbi ? s1b : s0b;
                mma_bf16(sa, qh[0], kh0, kh1);
                mma_bf16(sc, qh[1], kh2, kh3);
                mma_bf16(sa, qh[0], kl0, kl1);
                mma_bf16(sc, qh[1], kl2, kl3);
                mma_bf16(sa, ql[0], kh0, kh1);
                mma_bf16(sc, ql[1], kh2, kh3);
            }

            float e00 = __expf(s0a[0] + s0b[0] - gm0), e01 = __expf(s0a[1] + s0b[1] - gm0);
            float e02 = __expf(s0a[2] + s0b[2] - gm1), e03 = __expf(s0a[3] + s0b[3] - gm1);
            float e10 = __expf(s1a[0] + s1b[0] - gm0), e11 = __expf(s1a[1] + s1b[1] - gm0);
            float e12 = __expf(s1a[2] + s1b[2] - gm1), e13 = __expf(s1a[3] + s1b[3] - gm1);
            rs0 += e00 + e01 + e10 + e11;
            rs1 += e02 + e03 + e12 + e13;

            unsigned pa[4];
            pa[0] = cvt_f16x2(e01, e00);
            pa[1] = cvt_f16x2(e03, e02);
            pa[2] = cvt_f16x2(e11, e10);
            pa[3] = cvt_f16x2(e13, e12);

            uint32_t avh = vhb + vsw;
#pragma unroll
            for (int p = 0; p < 16; p++) {
                unsigned v0, v1, v2, v3;
                ldsm4(v0, v1, v2, v3, avh);
                mma_f16(o[2 * p],     pa, v0, v1);
                mma_f16(o[2 * p + 1], pa, v2, v3);
                avh += 16 * 128;
            }
        }
        __syncthreads();
    }

    rs0 += __shfl_xor_sync(0xffffffffu, rs0, 1);
    rs0 += __shfl_xor_sync(0xffffffffu, rs0, 2);
    rs1 += __shfl_xor_sync(0xffffffffu, rs1, 1);
    rs1 += __shfl_xor_sync(0xffffffffu, rs1, 2);
    const float inv0 = 1.0f / rs0;
    const float inv1 = 1.0f / rs1;

    const size_t r0b = ((size_t)b * NN + row0) * CH;
    const size_t r1b = ((size_t)b * NN + row0 + 8) * CH;
#pragma unroll
    for (int cb = 0; cb < 32; cb++) {
        size_t off = (size_t)(((cb ^ g) << 3) + t * 2);
        float v0 = o[cb][0] * inv0, v1 = o[cb][1] * inv0;
        unsigned h = cvt_bf16x2(v1, v0);
        unsigned l = cvt_bf16x2(v1 - f_hi(h), v0 - f_lo(h));
        *(unsigned*)(g_aoh + r0b + off) = h;
        *(unsigned*)(g_aol + r0b + off) = l;
        float u0 = o[cb][2] * inv1, u1 = o[cb][3] * inv1;
        unsigned h2 = cvt_bf16x2(u1, u0);
        unsigned l2 = cvt_bf16x2(u1 - f_hi(h2), u0 - f_lo(h2));
        *(unsigned*)(g_aoh + r1b + off) = h2;
        *(unsigned*)(g_aol + r1b + off) = l2;
    }
}

// ============================================================================
// Kernel 4: HMMA output projection + residual (unchanged)
// ============================================================================
__global__ void __launch_bounds__(256, 1)
final_kernel(const float* __restrict__ x,
             const float* __restrict__ bg,
             float* __restrict__ y)
{
    extern __shared__ __align__(1024) char smem[];
    const uint32_t sb  = smem_u32(smem);
    const uint32_t mb0 = sb;

    const int tid  = threadIdx.x;
    const int w    = tid >> 5;
    const int lane = tid & 31;
    const int g    = lane >> 2;
    const int t    = lane & 3;
    const int b    = blockIdx.y;
    const int n0   = blockIdx.x * 128;
    const int c0   = w * 32;

    if (tid == 0) MBAR_INIT(mb0, 1);
    __syncthreads();
    if (tid == 0) {
        MBAR_EXPECT_TX(mb0, 131072);
        bulk_g2s(sb + 1024,         g_aoh + ((size_t)b * NN + n0) * CH, 65536, mb0);
        bulk_g2s(sb + 1024 + 65536, g_aol + ((size_t)b * NN + n0) * CH, 65536, mb0);
    }

    float d[2][16][4];
#pragma unroll
    for (int mb = 0; mb < 2; mb++)
#pragma unroll
        for (int nb = 0; nb < 16; nb++) {
            d[mb][nb][0] = 0.f; d[mb][nb][1] = 0.f;
            d[mb][nb][2] = 0.f; d[mb][nb][3] = 0.f;
        }

    const uint32_t ao_row = sb + 1024
        + (uint32_t)(((lane >> 4) * 8 + (lane & 7)) * 512);
    const int chsel = (lane >> 3) & 1;
    const int r7 = lane & 7;

    unsigned ah[2][2][4], al[2][2][4];
    load_a_frags(ah[0], al[0], g_wgh, g_wgl, c0, g, t, 0);

    mbar_wait(mb0, 0);
    __syncthreads();

#pragma unroll
    for (int ks = 0; ks < 16; ks++) {
        const int cur = ks & 1, nxt = cur ^ 1;
        if (ks < 15)
            load_a_frags(ah[nxt], al[nxt], g_wgh, g_wgl, c0, g, t, ks + 1);

        const uint32_t sw = (uint32_t)((((2 * ks + chsel) ^ r7)) * 16);
#pragma unroll
        for (int p = 0; p < 8; p++) {
            uint32_t addr = ao_row + (uint32_t)(p * 16 * 512) + sw;
            unsigned bh0, bh1, bh2, bh3, bl0, bl1, bl2, bl3;
            ldsm4(bh0, bh1, bh2, bh3, addr);
            ldsm4(bl0, bl1, bl2, bl3, addr + 65536);
            GEMM_P_GROUP(d, ah[cur], al[cur],
                         bh0, bh1, bh2, bh3, bl0, bl1, bl2, bl3, p);
        }
    }

#pragma unroll
    for (int mb = 0; mb < 2; mb++) {
        int cA = c0 + mb * 16 + g;
        int cB = cA + 8;
        float bgA = bg[cA], bgB = bg[cB];
        const float* xA = x + ((size_t)b * CH + cA) * NN + n0 + t * 2;
        const float* xB = x + ((size_t)b * CH + cB) * NN + n0 + t * 2;
        float* yA = y + ((size_t)b * CH + cA) * NN + n0 + t * 2;
        float* yB = y + ((size_t)b * CH + cB) * NN + n0 + t * 2;
#pragma unroll
        for (int nb = 0; nb < 16; nb++) {
            float2 xr = *(const float2*)(xA + nb * 8);
            *(float2*)(yA + nb * 8) =
                make_float2(xr.x + bgA + d[mb][nb][0],
                            xr.y + bgA + d[mb][nb][1]);
            float2 xs2 = *(const float2*)(xB + nb * 8);
            *(float2*)(yB + nb * 8) =
                make_float2(xs2.x + bgB + d[mb][nb][2],
                            xs2.y + bgB + d[mb][nb][3]);
        }
    }
}

// ============================================================================
extern "C" void kernel_launch(void* const* d_in, const int* in_sizes, int n_in,
                              void* d_out, int out_size)
{
    const float* x  = (const float*)d_in[0];
    const float* wq = (const float*)d_in[1];
    const float* bq = (const float*)d_in[2];
    const float* wk = (const float*)d_in[3];
    const float* bk = (const float*)d_in[4];
    const float* wv = (const float*)d_in[5];
    const float* bv = (const float*)d_in[6];
    const float* wg = (const float*)d_in[7];
    const float* bg = (const float*)d_in[8];
    float* y = (float*)d_out;

    cudaFuncSetAttribute(attn_kernel,
                         cudaFuncAttributeMaxDynamicSharedMemorySize, SM_TOTAL);
    cudaFuncSetAttribute(rowmax_kernel,
                         cudaFuncAttributeMaxDynamicSharedMemorySize, RM_SM_TOTAL);
    cudaFuncSetAttribute(qkv_kernel,
                         cudaFuncAttributeMaxDynamicSharedMemorySize, GEMM_SM_TOTAL);
    cudaFuncSetAttribute(final_kernel,
                         cudaFuncAttributeMaxDynamicSharedMemorySize, GEMM_SM_TOTAL);

    wgprep_kernel  <<<CH * CH / 512, 256>>>(wg);
    wqkvprep_kernel<<<320 * CH / 512, 256>>>(wv, bv, wq, bq, wk, bk);
    xprep_kernel   <<<dim3(NN / 32, BATCH), 256>>>(x);
    qkv_kernel     <<<dim3(NN / 128, BATCH), 320, GEMM_SM_TOTAL>>>();
    rowmax_kernel  <<<dim3(NN / TQ, BATCH), 256, RM_SM_TOTAL>>>();
    attn_kernel    <<<dim3(NN / TQ, BATCH), 256, SM_TOTAL>>>();
    final_kernel   <<<dim3(NN / 128, BATCH), 256, GEMM_SM_TOTAL>>>(x, bg, y);
}

// round 15
// speedup vs baseline: 1.6182x; 1.0092x over previous
#include <cuda_runtime.h>
#include <cuda_bf16.h>
#include <cstdint>

#define BATCH 4
#define CH    256
#define CQK   32
#define NN    4096

#define TQ     128
#define TJ     64
#define NTILES (NN / TJ)   // 64

// ---- unified KV tile: [KH 64x40 bf16][KL 64x40 bf16][V 256x64 fp16]
#define KPAD       40
#define KV_TILE_EL 21504                  // 2-byte elements
#define KV_TILE_B  43008
#define KH_OFF     0                      // bytes
#define KL_OFF     5120
#define V_OFF      10240
#define SM_MB0  0
#define SM_MB1  8
#define SM_BUF  1024
#define SM_TOTAL (SM_BUF + 2 * KV_TILE_B)   // 87040

// rowmax kernel SMEM: [mbar pad 1024][2 x KH 5120]
#define RM_SM_TOTAL (1024 + 2 * 5120)

// GEMM kernels SMEM: [mbar pad 1024][B_hi 64KB][B_lo 64KB]
#define GEMM_SM_TOTAL (1024 + 2 * 65536)

// ---------------- scratch (device globals; no allocation allowed) ----------
__device__ __nv_bfloat16 g_qh[(size_t)BATCH * NN * CQK];
__device__ __nv_bfloat16 g_ql[(size_t)BATCH * NN * CQK];
__device__ __align__(128) __nv_bfloat16 g_kv[(size_t)BATCH * NTILES * KV_TILE_EL];
__device__ __align__(128) __nv_bfloat16 g_aoh[(size_t)BATCH * NN * CH];  // swizzled
__device__ __align__(128) __nv_bfloat16 g_aol[(size_t)BATCH * NN * CH];
__device__ __align__(128) __nv_bfloat16 g_xh[(size_t)BATCH * NN * CH];   // x^T swizzled
__device__ __align__(128) __nv_bfloat16 g_xl[(size_t)BATCH * NN * CH];
__device__ __nv_bfloat16 g_wgh[CH * CH];
__device__ __nv_bfloat16 g_wgl[CH * CH];
__device__ __nv_bfloat16 g_wh[320 * CH];   // [wv;wq;wk] hi
__device__ __nv_bfloat16 g_wl[320 * CH];
__device__ float         g_bqkv[320];
__device__ float         g_rmax[(size_t)BATCH * NN];

// ---------------- helpers ---------------------------------------------------
__device__ __forceinline__ unsigned cvt_bf16x2(float hi, float lo) {
    unsigned r;
    asm("cvt.rn.bf16x2.f32 %0, %1, %2;" : "=r"(r) : "f"(hi), "f"(lo));
    return r;
}
__device__ __forceinline__ unsigned cvt_f16x2(float hi, float lo) {
    unsigned r;
    asm("cvt.rn.f16x2.f32 %0, %1, %2;" : "=r"(r) : "f"(hi), "f"(lo));
    return r;
}
__device__ __forceinline__ float f_lo(unsigned u) { return __uint_as_float(u << 16); }
__device__ __forceinline__ float f_hi(unsigned u) { return __uint_as_float(u & 0xffff0000u); }

__device__ __forceinline__ uint32_t smem_u32(const void* p) {
    uint32_t a;
    asm("{ .reg .u64 t; cvta.to.shared.u64 t, %1; cvt.u32.u64 %0, t; }"
        : "=r"(a) : "l"(p));
    return a;
}

#define MBAR_INIT(addr, cnt) \
    asm volatile("mbarrier.init.shared.b64 [%0], %1;" :: "r"(addr), "r"(cnt) : "memory")
#define MBAR_EXPECT_TX(addr, bytes) \
    asm volatile("mbarrier.arrive.expect_tx.shared.b64 _, [%0], %1;" \
                 :: "r"(addr), "r"(bytes) : "memory")

__device__ __forceinline__ void mbar_wait(uint32_t addr, uint32_t parity) {
    asm volatile(
        "{\n\t.reg .pred P;\n\t"
        "WL_%=:\n\t"
        "mbarrier.try_wait.parity.acquire.cta.shared::cta.b64 P, [%0], %1, 0x989680;\n\t"
        "@P bra WD_%=;\n\t"
        "bra WL_%=;\n\t"
        "WD_%=:\n\t}"
        :: "r"(addr), "r"(parity) : "memory");
}
__device__ __forceinline__ void bulk_g2s(uint32_t dst, const void* src,
                                         uint32_t bytes, uint32_t mbar) {
    asm volatile(
        "cp.async.bulk.shared::cluster.global.mbarrier::complete_tx::bytes "
        "[%0], [%1], %2, [%3];"
        :: "r"(dst), "l"(src), "r"(bytes), "r"(mbar) : "memory");
}

__device__ __forceinline__ void ldsm4(unsigned& r0, unsigned& r1,
                                      unsigned& r2, unsigned& r3, uint32_t a) {
    asm volatile("ldmatrix.sync.aligned.m8n8.x4.shared.b16 {%0,%1,%2,%3}, [%4];"
                 : "=r"(r0), "=r"(r1), "=r"(r2), "=r"(r3) : "r"(a));
}

__device__ __forceinline__ void mma_bf16(float* d, const unsigned* a,
                                         unsigned b0, unsigned b1) {
    asm volatile(
        "mma.sync.aligned.m16n8k16.row.col.f32.bf16.bf16.f32 "
        "{%0,%1,%2,%3}, {%4,%5,%6,%7}, {%8,%9}, {%0,%1,%2,%3};"
        : "+f"(d[0]), "+f"(d[1]), "+f"(d[2]), "+f"(d[3])
        : "r"(a[0]), "r"(a[1]), "r"(a[2]), "r"(a[3]), "r"(b0), "r"(b1));
}
__device__ __forceinline__ void mma_f16(float* d, const unsigned* a,
                                        unsigned b0, unsigned b1) {
    asm volatile(
        "mma.sync.aligned.m16n8k16.row.col.f32.f16.f16.f32 "
        "{%0,%1,%2,%3}, {%4,%5,%6,%7}, {%8,%9}, {%0,%1,%2,%3};"
        : "+f"(d[0]), "+f"(d[1]), "+f"(d[2]), "+f"(d[3])
        : "r"(a[0]), "r"(a[1]), "r"(a[2]), "r"(a[3]), "r"(b0), "r"(b1));
}

// load A fragments (weights) for k-slice ks
__device__ __forceinline__ void load_a_frags(
    unsigned ah[2][4], unsigned al[2][4],
    const __nv_bfloat16* wh, const __nv_bfloat16* wl,
    int c0, int g, int t, int ks)
{
#pragma unroll
    for (int mb = 0; mb < 2; mb++) {
        int cr  = c0 + mb * 16 + g;
        int col = ks * 16 + t * 2;
        ah[mb][0] = *(const unsigned*)(wh + cr * CH + col);
        ah[mb][1] = *(const unsigned*)(wh + (cr + 8) * CH + col);
        ah[mb][2] = *(const unsigned*)(wh + cr * CH + col + 8);
        ah[mb][3] = *(const unsigned*)(wh + (cr + 8) * CH + col + 8);
        al[mb][0] = *(const unsigned*)(wl + cr * CH + col);
        al[mb][1] = *(const unsigned*)(wl + (cr + 8) * CH + col);
        al[mb][2] = *(const unsigned*)(wl + cr * CH + col + 8);
        al[mb][3] = *(const unsigned*)(wl + (cr + 8) * CH + col + 8);
    }
}

// 12 MMAs for one p-group
#define GEMM_P_GROUP(d, ah, al, bh0, bh1, bh2, bh3, bl0, bl1, bl2, bl3, p) \
    do {                                                                   \
        mma_bf16(d[0][2*(p)],     ah[0], bh0, bh1);                        \
        mma_bf16(d[0][2*(p) + 1], ah[0], bh2, bh3);                        \
        mma_bf16(d[1][2*(p)],     ah[1], bh0, bh1);                        \
        mma_bf16(d[1][2*(p) + 1], ah[1], bh2, bh3);                        \
        mma_bf16(d[0][2*(p)],     ah[0], bl0, bl1);                        \
        mma_bf16(d[0][2*(p) + 1], ah[0], bl2, bl3);                        \
        mma_bf16(d[1][2*(p)],     ah[1], bl0, bl1);                        \
        mma_bf16(d[1][2*(p) + 1], ah[1], bl2, bl3);                        \
        mma_bf16(d[0][2*(p)],     al[0], bh0, bh1);                        \
        mma_bf16(d[0][2*(p) + 1], al[0], bh2, bh3);                        \
        mma_bf16(d[1][2*(p)],     al[1], bh0, bh1);                        \
        mma_bf16(d[1][2*(p) + 1], al[1], bh2, bh3);                        \
    } while (0)

// ============================================================================
// Kernel P0: wg -> bf16 hi/lo
// ============================================================================
__global__ void __launch_bounds__(256)
wgprep_kernel(const float* __restrict__ wg)
{
    int i = blockIdx.x * 256 + threadIdx.x;
    float a = wg[2 * i], b = wg[2 * i + 1];
    unsigned h = cvt_bf16x2(b, a);
    unsigned l = cvt_bf16x2(b - f_hi(h), a - f_lo(h));
    *(unsigned*)(g_wgh + 2 * i) = h;
    *(unsigned*)(g_wgl + 2 * i) = l;
}

// ============================================================================
// Kernel P1: stacked [wv;wq;wk] -> bf16 hi/lo + combined bias
// ============================================================================
__global__ void __launch_bounds__(256)
wqkvprep_kernel(const float* __restrict__ wv, const float* __restrict__ bv,
                const float* __restrict__ wq, const float* __restrict__ bq,
                const float* __restrict__ wk, const float* __restrict__ bk)
{
    int i = blockIdx.x * 256 + threadIdx.x;
    int row  = i >> 7;
    int col2 = (i & 127) * 2;
    const float* src = (row < 256) ? wv + row * CH
                     : (row < 288) ? wq + (row - 256) * CH
                                   : wk + (row - 288) * CH;
    float a = src[col2], b = src[col2 + 1];
    unsigned h = cvt_bf16x2(b, a);
    unsigned l = cvt_bf16x2(b - f_hi(h), a - f_lo(h));
    *(unsigned*)(g_wh + row * CH + col2) = h;
    *(unsigned*)(g_wl + row * CH + col2) = l;
    if (i < 320)
        g_bqkv[i] = (i < 256) ? bv[i] : (i < 288) ? bq[i - 256] : bk[i - 288];
}

// ============================================================================
// Kernel P2: x [b][c][n] fp32 -> x^T [b][n][c] bf16 hi/lo, ldmatrix-swizzled
// ============================================================================
__global__ void __launch_bounds__(256)
xprep_kernel(const float* __restrict__ x)
{
    __shared__ __align__(16) float xs[CH * 33];
    const int b   = blockIdx.y;
    const int n0  = blockIdx.x * 32;
    const int tid = threadIdx.x;

    const float* xb = x + (size_t)b * CH * NN + n0;
    for (int idx = tid; idx < CH * 32; idx += 256) {
        int c = idx >> 5, n = idx & 31;
        xs[c * 33 + n] = xb[(size_t)c * NN + n];
    }
    __syncthreads();

    const int n   = tid & 31;
    const int g3  = tid >> 5;
    const int nsw = (n0 + n) & 7;
    __nv_bfloat16* dh = g_xh + ((size_t)b * NN + n0 + n) * CH;
    __nv_bfloat16* dl = g_xl + ((size_t)b * NN + n0 + n) * CH;

#pragma unroll
    for (int cc = 0; cc < 4; cc++) {
        int ch = g3 * 4 + cc;
        float v[8];
#pragma unroll
        for (int j = 0; j < 8; j++) v[j] = xs[(ch * 8 + j) * 33 + n];
        unsigned h[4], l[4];
#pragma unroll
        for (int j = 0; j < 4; j++) {
            h[j] = cvt_bf16x2(v[2 * j + 1], v[2 * j]);
            l[j] = cvt_bf16x2(v[2 * j + 1] - f_hi(h[j]), v[2 * j] - f_lo(h[j]));
        }
        int mch = (ch ^ nsw) << 3;
        *(uint4*)(dh + mch) = make_uint4(h[0], h[1], h[2], h[3]);
        *(uint4*)(dl + mch) = make_uint4(l[0], l[1], l[2], l[3]);
    }
}

// ============================================================================
// Kernel P3: fused q/k/v projection via HMMA; V stored as fp16 single.
// ============================================================================
__global__ void __launch_bounds__(320, 1)
qkv_kernel()
{
    extern __shared__ __align__(1024) char smem[];
    const uint32_t sb  = smem_u32(smem);
    const uint32_t mb0 = sb;

    const int tid  = threadIdx.x;
    const int w    = tid >> 5;
    const int lane = tid & 31;
    const int g    = lane >> 2;
    const int t    = lane & 3;
    const int b    = blockIdx.y;
    const int n0   = blockIdx.x * 128;
    const int c0   = w * 32;

    if (tid == 0) MBAR_INIT(mb0, 1);
    __syncthreads();
    if (tid == 0) {
        MBAR_EXPECT_TX(mb0, 131072);
        bulk_g2s(sb + 1024,         g_xh + ((size_t)b * NN + n0) * CH, 65536, mb0);
        bulk_g2s(sb + 1024 + 65536, g_xl + ((size_t)b * NN + n0) * CH, 65536, mb0);
    }

    float d[2][16][4];
#pragma unroll
    for (int mb = 0; mb < 2; mb++)
#pragma unroll
        for (int nb = 0; nb < 16; nb++) {
            d[mb][nb][0] = 0.f; d[mb][nb][1] = 0.f;
            d[mb][nb][2] = 0.f; d[mb][nb][3] = 0.f;
        }

    const uint32_t b_row = sb + 1024
        + (uint32_t)(((lane >> 4) * 8 + (lane & 7)) * 512);
    const int chsel = (lane >> 3) & 1;
    const int r7 = lane & 7;

    unsigned ah[2][2][4], al[2][2][4];
    load_a_frags(ah[0], al[0], g_wh, g_wl, c0, g, t, 0);

    mbar_wait(mb0, 0);
    __syncthreads();

#pragma unroll
    for (int ks = 0; ks < 16; ks++) {
        const int cur = ks & 1, nxt = cur ^ 1;
        if (ks < 15)
            load_a_frags(ah[nxt], al[nxt], g_wh, g_wl, c0, g, t, ks + 1);

        const uint32_t sw = (uint32_t)(((2 * ks + chsel) ^ r7) * 16);
#pragma unroll
        for (int p = 0; p < 8; p++) {
            uint32_t addr = b_row + (uint32_t)(p * 16 * 512) + sw;
            unsigned bh0, bh1, bh2, bh3, bl0, bl1, bl2, bl3;
            ldsm4(bh0, bh1, bh2, bh3, addr);
            ldsm4(bl0, bl1, bl2, bl3, addr + 65536);
            GEMM_P_GROUP(d, ah[cur], al[cur],
                         bh0, bh1, bh2, bh3, bl0, bl1, bl2, bl3, p);
        }
    }

    // ---- epilogue: scatter to V fp16 (warps 0-7), q (warp 8), K (warp 9) ----
    const size_t kvbase = (size_t)b * NTILES * KV_TILE_EL;
#pragma unroll
    for (int mb = 0; mb < 2; mb++) {
        int rA = c0 + mb * 16 + g;
        int rB = rA + 8;
        float biasA = g_bqkv[rA], biasB = g_bqkv[rB];
#pragma unroll
        for (int nb = 0; nb < 16; nb++) {
            int n    = n0 + nb * 8 + t * 2;
            int tile = n >> 6;
            int jt   = n & 63;
            size_t kvb = kvbase + (size_t)tile * KV_TILE_EL;
            float vA0 = d[mb][nb][0] + biasA, vA1 = d[mb][nb][1] + biasA;
            float vB0 = d[mb][nb][2] + biasB, vB1 = d[mb][nb][3] + biasB;
            if (w < 8) {
                size_t vb = kvb + 5120;
                size_t offA = (size_t)rA * 64 + (((jt >> 3) ^ (rA & 7)) << 3) + (jt & 7);
                *(unsigned*)(g_kv + vb + offA) = cvt_f16x2(vA1, vA0);
                size_t offB = (size_t)rB * 64 + (((jt >> 3) ^ (rB & 7)) << 3) + (jt & 7);
                *(unsigned*)(g_kv + vb + offB) = cvt_f16x2(vB1, vB0);
            } else if (w == 8) {
                int dA = rA - 256, dB = rB - 256;
                size_t r0 = ((size_t)b * NN + n) * CQK;
                size_t r1 = r0 + CQK;
                __nv_bfloat16 hA0 = __float2bfloat16(vA0);
                __nv_bfloat16 hA1 = __float2bfloat16(vA1);
                g_qh[r0 + dA] = hA0; g_ql[r0 + dA] = __float2bfloat16(vA0 - __bfloat162float(hA0));
                g_qh[r1 + dA] = hA1; g_ql[r1 + dA] = __float2bfloat16(vA1 - __bfloat162float(hA1));
                __nv_bfloat16 hB0 = __float2bfloat16(vB0);
                __nv_bfloat16 hB1 = __float2bfloat16(vB1);
                g_qh[r0 + dB] = hB0; g_ql[r0 + dB] = __float2bfloat16(vB0 - __bfloat162float(hB0));
                g_qh[r1 + dB] = hB1; g_ql[r1 + dB] = __float2bfloat16(vB1 - __bfloat162float(hB1));
            } else {
                int dA = rA - 288, dB = rB - 288;
                size_t k0 = kvb + (size_t)jt * KPAD;
                size_t k1 = k0 + KPAD;
                __nv_bfloat16 hA0 = __float2bfloat16(vA0);
                __nv_bfloat16 hA1 = __float2bfloat16(vA1);
                g_kv[k0 + dA] = hA0; g_kv[k0 + 2560 + dA] = __float2bfloat16(vA0 - __bfloat162float(hA0));
                g_kv[k1 + dA] = hA1; g_kv[k1 + 2560 + dA] = __float2bfloat16(vA1 - __bfloat162float(hA1));
                __nv_bfloat16 hB0 = __float2bfloat16(vB0);
                __nv_bfloat16 hB1 = __float2bfloat16(vB1);
                g_kv[k0 + dB] = hB0; g_kv[k0 + 2560 + dB] = __float2bfloat16(vB0 - __bfloat162float(hB0));
                g_kv[k1 + dB] = hB1; g_kv[k1 + 2560 + dB] = __float2bfloat16(vB1 - __bfloat162float(hB1));
            }
        }
    }
}

// ============================================================================
// Kernel P4: row max of energies (1-pass bf16 QK). Writes g_rmax[b][n].
// ============================================================================
__global__ void __launch_bounds__(256, 1)
rowmax_kernel()
{
    extern __shared__ __align__(1024) char smem[];
    const uint32_t sb  = smem_u32(smem);
    const uint32_t mb0 = sb + SM_MB0;
    const uint32_t mb1 = sb + SM_MB1;

    const int tid  = threadIdx.x;
    const int w    = tid >> 5;
    const int lane = tid & 31;
    const int g    = lane >> 2;
    const int t    = lane & 3;
    const int b    = blockIdx.y;
    const int q0   = blockIdx.x * TQ;
    const int row0 = q0 + w * 16 + g;

    if (tid == 0) { MBAR_INIT(mb0, 1); MBAR_INIT(mb1, 1); }
    __syncthreads();

    const __nv_bfloat16* kv_src = g_kv + (size_t)b * NTILES * KV_TILE_EL;
    const uint32_t k_lm = (uint32_t)(((lane & 7) * KPAD + (lane >> 3) * 8) * 2);

    unsigned qh[2][4];
    {
        const __nv_bfloat16* qhp = g_qh + (size_t)b * NN * CQK;
#pragma unroll
        for (int kq = 0; kq < 2; kq++) {
            int c0 = kq * 16 + t * 2;
            qh[kq][0] = *(const unsigned*)(qhp + (size_t)row0 * CQK + c0);
            qh[kq][1] = *(const unsigned*)(qhp + (size_t)(row0 + 8) * CQK + c0);
            qh[kq][2] = *(const unsigned*)(qhp + (size_t)row0 * CQK + c0 + 8);
            qh[kq][3] = *(const unsigned*)(qhp + (size_t)(row0 + 8) * CQK + c0 + 8);
        }
    }

    float m0 = -1e30f, m1 = -1e30f;

    if (tid == 0) {
        MBAR_EXPECT_TX(mb0, 5120);
        bulk_g2s(sb + SM_BUF, kv_src, 5120, mb0);
    }

    for (int tl = 0; tl < NTILES; tl++) {
        if (tl + 1 < NTILES && tid == 0) {
            uint32_t mb = ((tl + 1) & 1) ? mb1 : mb0;
            MBAR_EXPECT_TX(mb, 5120);
            bulk_g2s(sb + SM_BUF + ((tl + 1) & 1) * 5120,
                     kv_src + (size_t)(tl + 1) * KV_TILE_EL, 5120, mb);
        }
        mbar_wait((tl & 1) ? mb1 : mb0, (tl >> 1) & 1);

        const uint32_t khb = sb + SM_BUF + (tl & 1) * 5120 + k_lm;

#pragma unroll
        for (int jb = 0; jb < 8; jb++) {
            unsigned kh0, kh1, kh2, kh3;
            ldsm4(kh0, kh1, kh2, kh3, khb + (uint32_t)(jb * 8 * KPAD * 2));
            float sA[4] = {0.f, 0.f, 0.f, 0.f};
            float sB[4] = {0.f, 0.f, 0.f, 0.f};
            mma_bf16(sA, qh[0], kh0, kh1);
            mma_bf16(sB, qh[1], kh2, kh3);
            m0 = fmaxf(m0, fmaxf(sA[0] + sB[0], sA[1] + sB[1]));
            m1 = fmaxf(m1, fmaxf(sA[2] + sB[2], sA[3] + sB[3]));
        }
        __syncthreads();
    }

    m0 = fmaxf(m0, __shfl_xor_sync(0xffffffffu, m0, 1));
    m0 = fmaxf(m0, __shfl_xor_sync(0xffffffffu, m0, 2));
    m1 = fmaxf(m1, __shfl_xor_sync(0xffffffffu, m1, 1));
    m1 = fmaxf(m1, __shfl_xor_sync(0xffffffffu, m1, 2));
    if (t == 0) {
        g_rmax[(size_t)b * NN + row0]     = m0;
        g_rmax[(size_t)b * NN + row0 + 8] = m1;
    }
}

// ============================================================================
// Kernel 3: HMMA flash attention; QK pipelined one kb ahead of exp/PV.
// ============================================================================
__global__ void __launch_bounds__(256, 1)
attn_kernel()
{
    extern __shared__ __align__(1024) char smem[];

    const int tid  = threadIdx.x;
    const int w    = tid >> 5;
    const int lane = tid & 31;
    const int g    = lane >> 2;
    const int t    = lane & 3;
    const int b    = blockIdx.y;
    const int q0   = blockIdx.x * TQ;
    const int row0 = q0 + w * 16 + g;

    const uint32_t sb  = smem_u32(smem);
    const uint32_t mb0 = sb + SM_MB0;
    const uint32_t mb1 = sb + SM_MB1;

    if (tid == 0) { MBAR_INIT(mb0, 1); MBAR_INIT(mb1, 1); }
    __syncthreads();

    const __nv_bfloat16* kv_src = g_kv + (size_t)b * NTILES * KV_TILE_EL;

    const uint32_t k_lm = (uint32_t)(((lane & 7) * KPAD + (lane >> 3) * 8) * 2);
    const int vm = lane >> 3;
    const int vr = lane & 7;
    const uint32_t v_row = (uint32_t)(((vm >> 1) * 8 + vr) * 128);

    const float gm0 = g_rmax[(size_t)b * NN + row0];
    const float gm1 = g_rmax[(size_t)b * NN + row0 + 8];

    unsigned qh[2][4], ql[2][4];
    {
        const __nv_bfloat16* qhp = g_qh + (size_t)b * NN * CQK;
        const __nv_bfloat16* qlp = g_ql + (size_t)b * NN * CQK;
#pragma unroll
        for (int kq = 0; kq < 2; kq++) {
            int c0 = kq * 16 + t * 2;
            qh[kq][0] = *(const unsigned*)(qhp + (size_t)row0 * CQK + c0);
            qh[kq][1] = *(const unsigned*)(qhp + (size_t)(row0 + 8) * CQK + c0);
            qh[kq][2] = *(const unsigned*)(qhp + (size_t)row0 * CQK + c0 + 8);
            qh[kq][3] = *(const unsigned*)(qhp + (size_t)(row0 + 8) * CQK + c0 + 8);
            ql[kq][0] = *(const unsigned*)(qlp + (size_t)row0 * CQK + c0);
            ql[kq][1] = *(const unsigned*)(qlp + (size_t)(row0 + 8) * CQK + c0);
            ql[kq][2] = *(const unsigned*)(qlp + (size_t)row0 * CQK + c0 + 8);
            ql[kq][3] = *(const unsigned*)(qlp + (size_t)(row0 + 8) * CQK + c0 + 8);
        }
    }

    float o[32][4];
#pragma unroll
    for (int cb = 0; cb < 32; cb++) {
        o[cb][0] = 0.f; o[cb][1] = 0.f; o[cb][2] = 0.f; o[cb][3] = 0.f;
    }
    float rs0 = 0.f, rs1 = 0.f;

    if (tid == 0) {
        MBAR_EXPECT_TX(mb0, KV_TILE_B);
        bulk_g2s(sb + SM_BUF, kv_src, KV_TILE_B, mb0);
    }

    // S double buffer: [buf][acc 0..3][4]
    float s[2][4][4];

    for (int tl = 0; tl < NTILES; tl++) {
        if (tl + 1 < NTILES && tid == 0) {
            uint32_t mb = ((tl + 1) & 1) ? mb1 : mb0;
            MBAR_EXPECT_TX(mb, KV_TILE_B);
            bulk_g2s(sb + SM_BUF + ((tl + 1) & 1) * KV_TILE_B,
                     kv_src + (size_t)(tl + 1) * KV_TILE_EL, KV_TILE_B, mb);
        }
        mbar_wait((tl & 1) ? mb1 : mb0, (tl >> 1) & 1);
        __syncthreads();

        const uint32_t bb  = sb + SM_BUF + (tl & 1) * KV_TILE_B;
        const uint32_t khb = bb + KH_OFF + k_lm;
        const uint32_t klb = bb + KL_OFF + k_lm;
        const uint32_t vhb = bb + V_OFF + v_row;

        // ---- QK(0) prologue ----
#pragma unroll
        for (int a = 0; a < 4; a++)
#pragma unroll
            for (int i = 0; i < 4; i++) s[0][a][i] = 0.f;
#pragma unroll
        for (int jbi = 0; jbi < 2; jbi++) {
            const uint32_t koff = (uint32_t)(jbi * 8 * KPAD * 2);
            unsigned kh0, kh1, kh2, kh3, kl0, kl1, kl2, kl3;
            ldsm4(kh0, kh1, kh2, kh3, khb + koff);
            ldsm4(kl0, kl1, kl2, kl3, klb + koff);
            float* sa = s[0][jbi * 2];
            float* sc = s[0][jbi * 2 + 1];
            mma_bf16(sa, qh[0], kh0, kh1);
            mma_bf16(sc, qh[1], kh2, kh3);
            mma_bf16(sa, qh[0], kl0, kl1);
            mma_bf16(sc, qh[1], kl2, kl3);
            mma_bf16(sa, ql[0], kh0, kh1);
            mma_bf16(sc, ql[1], kh2, kh3);
        }

#pragma unroll
        for (int kb = 0; kb < 4; kb++) {
            const int cur = kb & 1, nxt = cur ^ 1;

            // ---- issue QK(kb+1) first (fills tensor pipe through exp) ----
            if (kb < 3) {
#pragma unroll
                for (int a = 0; a < 4; a++)
#pragma unroll
                    for (int i = 0; i < 4; i++) s[nxt][a][i] = 0.f;
#pragma unroll
                for (int jbi = 0; jbi < 2; jbi++) {
                    const uint32_t koff =
                        (uint32_t)(((kb + 1) * 2 + jbi) * 8 * KPAD * 2);
                    unsigned kh0, kh1, kh2, kh3, kl0, kl1, kl2, kl3;
                    ldsm4(kh0, kh1, kh2, kh3, khb + koff);
                    ldsm4(kl0, kl1, kl2, kl3, klb + koff);
                    float* sa = s[nxt][jbi * 2];
                    float* sc = s[nxt][jbi * 2 + 1];
                    mma_bf16(sa, qh[0], kh0, kh1);
                    mma_bf16(sc, qh[1], kh2, kh3);
                    mma_bf16(sa, qh[0], kl0, kl1);
                    mma_bf16(sc, qh[1], kl2, kl3);
                    mma_bf16(sa, ql[0], kh0, kh1);
                    mma_bf16(sc, ql[1], kh2, kh3);
                }
            }

            // ---- exp(kb) (MUFU overlaps QK(kb+1) in tensor pipe) ----
            float* s0a = s[cur][0];
            float* s0b = s[cur][1];
            float* s1a = s[cur][2];
            float* s1b = s[cur][3];
            float e00 = __expf(s0a[0] + s0b[0] - gm0), e01 = __expf(s0a[1] + s0b[1] - gm0);
            float e02 = __expf(s0a[2] + s0b[2] - gm1), e03 = __expf(s0a[3] + s0b[3] - gm1);
            float e10 = __expf(s1a[0] + s1b[0] - gm0), e11 = __expf(s1a[1] + s1b[1] - gm0);
            float e12 = __expf(s1a[2] + s1b[2] - gm1), e13 = __expf(s1a[3] + s1b[3] - gm1);
            rs0 += e00 + e01 + e10 + e11;
            rs1 += e02 + e03 + e12 + e13;

            unsigned pa[4];
            pa[0] = cvt_f16x2(e01, e00);
            pa[1] = cvt_f16x2(e03, e02);
            pa[2] = cvt_f16x2(e11, e10);
            pa[3] = cvt_f16x2(e13, e12);

            // ---- PV(kb) ----
            const uint32_t vsw = (uint32_t)(((kb * 2 + (vm & 1)) ^ vr) * 16);
            uint32_t avh = vhb + vsw;
#pragma unroll
            for (int p = 0; p < 16; p++) {
                unsigned v0, v1, v2, v3;
                ldsm4(v0, v1, v2, v3, avh);
                mma_f16(o[2 * p],     pa, v0, v1);
                mma_f16(o[2 * p + 1], pa, v2, v3);
                avh += 16 * 128;
            }
        }
        __syncthreads();
    }

    rs0 += __shfl_xor_sync(0xffffffffu, rs0, 1);
    rs0 += __shfl_xor_sync(0xffffffffu, rs0, 2);
    rs1 += __shfl_xor_sync(0xffffffffu, rs1, 1);
    rs1 += __shfl_xor_sync(0xffffffffu, rs1, 2);
    const float inv0 = 1.0f / rs0;
    const float inv1 = 1.0f / rs1;

    const size_t r0b = ((size_t)b * NN + row0) * CH;
    const size_t r1b = ((size_t)b * NN + row0 + 8) * CH;
#pragma unroll
    for (int cb = 0; cb < 32; cb++) {
        size_t off = (size_t)(((cb ^ g) << 3) + t * 2);
        float v0 = o[cb][0] * inv0, v1 = o[cb][1] * inv0;
        unsigned h = cvt_bf16x2(v1, v0);
        unsigned l = cvt_bf16x2(v1 - f_hi(h), v0 - f_lo(h));
        *(unsigned*)(g_aoh + r0b + off) = h;
        *(unsigned*)(g_aol + r0b + off) = l;
        float u0 = o[cb][2] * inv1, u1 = o[cb][3] * inv1;
        unsigned h2 = cvt_bf16x2(u1, u0);
        unsigned l2 = cvt_bf16x2(u1 - f_hi(h2), u0 - f_lo(h2));
        *(unsigned*)(g_aoh + r1b + off) = h2;
        *(unsigned*)(g_aol + r1b + off) = l2;
    }
}

// ============================================================================
// Kernel 4: HMMA output projection + residual (unchanged)
// ============================================================================
__global__ void __launch_bounds__(256, 1)
final_kernel(const float* __restrict__ x,
             const float* __restrict__ bg,
             float* __restrict__ y)
{
    extern __shared__ __align__(1024) char smem[];
    const uint32_t sb  = smem_u32(smem);
    const uint32_t mb0 = sb;

    const int tid  = threadIdx.x;
    const int w    = tid >> 5;
    const int lane = tid & 31;
    const int g    = lane >> 2;
    const int t    = lane & 3;
    const int b    = blockIdx.y;
    const int n0   = blockIdx.x * 128;
    const int c0   = w * 32;

    if (tid == 0) MBAR_INIT(mb0, 1);
    __syncthreads();
    if (tid == 0) {
        MBAR_EXPECT_TX(mb0, 131072);
        bulk_g2s(sb + 1024,         g_aoh + ((size_t)b * NN + n0) * CH, 65536, mb0);
        bulk_g2s(sb + 1024 + 65536, g_aol + ((size_t)b * NN + n0) * CH, 65536, mb0);
    }

    float d[2][16][4];
#pragma unroll
    for (int mb = 0; mb < 2; mb++)
#pragma unroll
        for (int nb = 0; nb < 16; nb++) {
            d[mb][nb][0] = 0.f; d[mb][nb][1] = 0.f;
            d[mb][nb][2] = 0.f; d[mb][nb][3] = 0.f;
        }

    const uint32_t ao_row = sb + 1024
        + (uint32_t)(((lane >> 4) * 8 + (lane & 7)) * 512);
    const int chsel = (lane >> 3) & 1;
    const int r7 = lane & 7;

    unsigned ah[2][2][4], al[2][2][4];
    load_a_frags(ah[0], al[0], g_wgh, g_wgl, c0, g, t, 0);

    mbar_wait(mb0, 0);
    __syncthreads();

#pragma unroll
    for (int ks = 0; ks < 16; ks++) {
        const int cur = ks & 1, nxt = cur ^ 1;
        if (ks < 15)
            load_a_frags(ah[nxt], al[nxt], g_wgh, g_wgl, c0, g, t, ks + 1);

        const uint32_t sw = (uint32_t)((((2 * ks + chsel) ^ r7)) * 16);
#pragma unroll
        for (int p = 0; p < 8; p++) {
            uint32_t addr = ao_row + (uint32_t)(p * 16 * 512) + sw;
            unsigned bh0, bh1, bh2, bh3, bl0, bl1, bl2, bl3;
            ldsm4(bh0, bh1, bh2, bh3, addr);
            ldsm4(bl0, bl1, bl2, bl3, addr + 65536);
            GEMM_P_GROUP(d, ah[cur], al[cur],
                         bh0, bh1, bh2, bh3, bl0, bl1, bl2, bl3, p);
        }
    }

#pragma unroll
    for (int mb = 0; mb < 2; mb++) {
        int cA = c0 + mb * 16 + g;
        int cB = cA + 8;
        float bgA = bg[cA], bgB = bg[cB];
        const float* xA = x + ((size_t)b * CH + cA) * NN + n0 + t * 2;
        const float* xB = x + ((size_t)b * CH + cB) * NN + n0 + t * 2;
        float* yA = y + ((size_t)b * CH + cA) * NN + n0 + t * 2;
        float* yB = y + ((size_t)b * CH + cB) * NN + n0 + t * 2;
#pragma unroll
        for (int nb = 0; nb < 16; nb++) {
            float2 xr = *(const float2*)(xA + nb * 8);
            *(float2*)(yA + nb * 8) =
                make_float2(xr.x + bgA + d[mb][nb][0],
                            xr.y + bgA + d[mb][nb][1]);
            float2 xs2 = *(const float2*)(xB + nb * 8);
            *(float2*)(yB + nb * 8) =
                make_float2(xs2.x + bgB + d[mb][nb][2],
                            xs2.y + bgB + d[mb][nb][3]);
        }
    }
}

// ============================================================================
extern "C" void kernel_launch(void* const* d_in, const int* in_sizes, int n_in,
                              void* d_out, int out_size)
{
    const float* x  = (const float*)d_in[0];
    const float* wq = (const float*)d_in[1];
    const float* bq = (const float*)d_in[2];
    const float* wk = (const float*)d_in[3];
    const float* bk = (const float*)d_in[4];
    const float* wv = (const float*)d_in[5];
    const float* bv = (const float*)d_in[6];
    const float* wg = (const float*)d_in[7];
    const float* bg = (const float*)d_in[8];
    float* y = (float*)d_out;

    cudaFuncSetAttribute(attn_kernel,
                         cudaFuncAttributeMaxDynamicSharedMemorySize, SM_TOTAL);
    cudaFuncSetAttribute(rowmax_kernel,
                         cudaFuncAttributeMaxDynamicSharedMemorySize, RM_SM_TOTAL);
    cudaFuncSetAttribute(qkv_kernel,
                         cudaFuncAttributeMaxDynamicSharedMemorySize, GEMM_SM_TOTAL);
    cudaFuncSetAttribute(final_kernel,
                         cudaFuncAttributeMaxDynamicSharedMemorySize, GEMM_SM_TOTAL);

    wgprep_kernel  <<<CH * CH / 512, 256>>>(wg);
    wqkvprep_kernel<<<320 * CH / 512, 256>>>(wv, bv, wq, bq, wk, bk);
    xprep_kernel   <<<dim3(NN / 32, BATCH), 256>>>(x);
    qkv_kernel     <<<dim3(NN / 128, BATCH), 320, GEMM_SM_TOTAL>>>();
    rowmax_kernel  <<<dim3(NN / TQ, BATCH), 256, RM_SM_TOTAL>>>();
    attn_kernel    <<<dim3(NN / TQ, BATCH), 256, SM_TOTAL>>>();
    final_kernel   <<<dim3(NN / 128, BATCH), 256, GEMM_SM_TOTAL>>>(x, bg, y);
}

// round 16
// speedup vs baseline: 1.7170x; 1.0610x over previous
#include <cuda_runtime.h>
#include <cuda_bf16.h>
#include <cstdint>

#define BATCH 4
#define CH    256
#define CQK   32
#define NN    4096

#define TQ     128
#define TJ     64
#define NTILES (NN / TJ)   // 64

// ---- unified KV tile: [KH 64x40 bf16][KL 64x40 bf16][V 256x64 fp16]
#define KPAD       40
#define KV_TILE_EL 21504
#define KV_TILE_B  43008
#define KH_OFF     0
#define KL_OFF     5120
#define V_OFF      10240
#define SM_MB0  0
#define SM_MB1  8
#define SM_BUF  1024
// fused attn SMEM: [mbar 1024][AO hi 64KB | AO lo 64KB], KV buffers overlay AO
#define SM_AO_HI   1024
#define SM_AO_LO   (1024 + 65536)
#define SM_TOTAL_F (1024 + 131072)      // 132096

// rowmax kernel SMEM: [mbar pad 1024][2 x KH 5120]
#define RM_SM_TOTAL (1024 + 2 * 5120)

// qkv kernel SMEM: [mbar pad 1024][B_hi 64KB][B_lo 64KB]
#define GEMM_SM_TOTAL (1024 + 2 * 65536)

// ---------------- scratch (device globals; no allocation allowed) ----------
__device__ __nv_bfloat16 g_qh[(size_t)BATCH * NN * CQK];
__device__ __nv_bfloat16 g_ql[(size_t)BATCH * NN * CQK];
__device__ __align__(128) __nv_bfloat16 g_kv[(size_t)BATCH * NTILES * KV_TILE_EL];
__device__ __align__(128) __nv_bfloat16 g_xh[(size_t)BATCH * NN * CH];   // x^T swizzled
__device__ __align__(128) __nv_bfloat16 g_xl[(size_t)BATCH * NN * CH];
__device__ __nv_bfloat16 g_wgh[CH * CH];
__device__ __nv_bfloat16 g_wgl[CH * CH];
__device__ __nv_bfloat16 g_wh[320 * CH];   // [wv;wq;wk] hi
__device__ __nv_bfloat16 g_wl[320 * CH];
__device__ float         g_bqkv[320];
__device__ float         g_rmax[(size_t)BATCH * NN];

// ---------------- helpers ---------------------------------------------------
__device__ __forceinline__ unsigned cvt_bf16x2(float hi, float lo) {
    unsigned r;
    asm("cvt.rn.bf16x2.f32 %0, %1, %2;" : "=r"(r) : "f"(hi), "f"(lo));
    return r;
}
__device__ __forceinline__ unsigned cvt_f16x2(float hi, float lo) {
    unsigned r;
    asm("cvt.rn.f16x2.f32 %0, %1, %2;" : "=r"(r) : "f"(hi), "f"(lo));
    return r;
}
__device__ __forceinline__ float f_lo(unsigned u) { return __uint_as_float(u << 16); }
__device__ __forceinline__ float f_hi(unsigned u) { return __uint_as_float(u & 0xffff0000u); }

__device__ __forceinline__ uint32_t smem_u32(const void* p) {
    uint32_t a;
    asm("{ .reg .u64 t; cvta.to.shared.u64 t, %1; cvt.u32.u64 %0, t; }"
        : "=r"(a) : "l"(p));
    return a;
}

#define MBAR_INIT(addr, cnt) \
    asm volatile("mbarrier.init.shared.b64 [%0], %1;" :: "r"(addr), "r"(cnt) : "memory")
#define MBAR_EXPECT_TX(addr, bytes) \
    asm volatile("mbarrier.arrive.expect_tx.shared.b64 _, [%0], %1;" \
                 :: "r"(addr), "r"(bytes) : "memory")

__device__ __forceinline__ void mbar_wait(uint32_t addr, uint32_t parity) {
    asm volatile(
        "{\n\t.reg .pred P;\n\t"
        "WL_%=:\n\t"
        "mbarrier.try_wait.parity.acquire.cta.shared::cta.b64 P, [%0], %1, 0x989680;\n\t"
        "@P bra WD_%=;\n\t"
        "bra WL_%=;\n\t"
        "WD_%=:\n\t}"
        :: "r"(addr), "r"(parity) : "memory");
}
__device__ __forceinline__ void bulk_g2s(uint32_t dst, const void* src,
                                         uint32_t bytes, uint32_t mbar) {
    asm volatile(
        "cp.async.bulk.shared::cluster.global.mbarrier::complete_tx::bytes "
        "[%0], [%1], %2, [%3];"
        :: "r"(dst), "l"(src), "r"(bytes), "r"(mbar) : "memory");
}

__device__ __forceinline__ void ldsm4(unsigned& r0, unsigned& r1,
                                      unsigned& r2, unsigned& r3, uint32_t a) {
    asm volatile("ldmatrix.sync.aligned.m8n8.x4.shared.b16 {%0,%1,%2,%3}, [%4];"
                 : "=r"(r0), "=r"(r1), "=r"(r2), "=r"(r3) : "r"(a));
}

__device__ __forceinline__ void mma_bf16(float* d, const unsigned* a,
                                         unsigned b0, unsigned b1) {
    asm volatile(
        "mma.sync.aligned.m16n8k16.row.col.f32.bf16.bf16.f32 "
        "{%0,%1,%2,%3}, {%4,%5,%6,%7}, {%8,%9}, {%0,%1,%2,%3};"
        : "+f"(d[0]), "+f"(d[1]), "+f"(d[2]), "+f"(d[3])
        : "r"(a[0]), "r"(a[1]), "r"(a[2]), "r"(a[3]), "r"(b0), "r"(b1));
}
__device__ __forceinline__ void mma_f16(float* d, const unsigned* a,
                                        unsigned b0, unsigned b1) {
    asm volatile(
        "mma.sync.aligned.m16n8k16.row.col.f32.f16.f16.f32 "
        "{%0,%1,%2,%3}, {%4,%5,%6,%7}, {%8,%9}, {%0,%1,%2,%3};"
        : "+f"(d[0]), "+f"(d[1]), "+f"(d[2]), "+f"(d[3])
        : "r"(a[0]), "r"(a[1]), "r"(a[2]), "r"(a[3]), "r"(b0), "r"(b1));
}

// load A fragments (weights) for k-slice ks
__device__ __forceinline__ void load_a_frags(
    unsigned ah[2][4], unsigned al[2][4],
    const __nv_bfloat16* wh, const __nv_bfloat16* wl,
    int c0, int g, int t, int ks)
{
#pragma unroll
    for (int mb = 0; mb < 2; mb++) {
        int cr  = c0 + mb * 16 + g;
        int col = ks * 16 + t * 2;
        ah[mb][0] = *(const unsigned*)(wh + cr * CH + col);
        ah[mb][1] = *(const unsigned*)(wh + (cr + 8) * CH + col);
        ah[mb][2] = *(const unsigned*)(wh + cr * CH + col + 8);
        ah[mb][3] = *(const unsigned*)(wh + (cr + 8) * CH + col + 8);
        al[mb][0] = *(const unsigned*)(wl + cr * CH + col);
        al[mb][1] = *(const unsigned*)(wl + (cr + 8) * CH + col);
        al[mb][2] = *(const unsigned*)(wl + cr * CH + col + 8);
        al[mb][3] = *(const unsigned*)(wl + (cr + 8) * CH + col + 8);
    }
}

// 12 MMAs for one p-group
#define GEMM_P_GROUP(d, ah, al, bh0, bh1, bh2, bh3, bl0, bl1, bl2, bl3, p) \
    do {                                                                   \
        mma_bf16(d[0][2*(p)],     ah[0], bh0, bh1);                        \
        mma_bf16(d[0][2*(p) + 1], ah[0], bh2, bh3);                        \
        mma_bf16(d[1][2*(p)],     ah[1], bh0, bh1);                        \
        mma_bf16(d[1][2*(p) + 1], ah[1], bh2, bh3);                        \
        mma_bf16(d[0][2*(p)],     ah[0], bl0, bl1);                        \
        mma_bf16(d[0][2*(p) + 1], ah[0], bl2, bl3);                        \
        mma_bf16(d[1][2*(p)],     ah[1], bl0, bl1);                        \
        mma_bf16(d[1][2*(p) + 1], ah[1], bl2, bl3);                        \
        mma_bf16(d[0][2*(p)],     al[0], bh0, bh1);                        \
        mma_bf16(d[0][2*(p) + 1], al[0], bh2, bh3);                        \
        mma_bf16(d[1][2*(p)],     al[1], bh0, bh1);                        \
        mma_bf16(d[1][2*(p) + 1], al[1], bh2, bh3);                        \
    } while (0)

// ============================================================================
// Kernel P0: wg -> bf16 hi/lo
// ============================================================================
__global__ void __launch_bounds__(256)
wgprep_kernel(const float* __restrict__ wg)
{
    int i = blockIdx.x * 256 + threadIdx.x;
    float a = wg[2 * i], b = wg[2 * i + 1];
    unsigned h = cvt_bf16x2(b, a);
    unsigned l = cvt_bf16x2(b - f_hi(h), a - f_lo(h));
    *(unsigned*)(g_wgh + 2 * i) = h;
    *(unsigned*)(g_wgl + 2 * i) = l;
}

// ============================================================================
// Kernel P1: stacked [wv;wq;wk] -> bf16 hi/lo + combined bias
// ============================================================================
__global__ void __launch_bounds__(256)
wqkvprep_kernel(const float* __restrict__ wv, const float* __restrict__ bv,
                const float* __restrict__ wq, const float* __restrict__ bq,
                const float* __restrict__ wk, const float* __restrict__ bk)
{
    int i = blockIdx.x * 256 + threadIdx.x;
    int row  = i >> 7;
    int col2 = (i & 127) * 2;
    const float* src = (row < 256) ? wv + row * CH
                     : (row < 288) ? wq + (row - 256) * CH
                                   : wk + (row - 288) * CH;
    float a = src[col2], b = src[col2 + 1];
    unsigned h = cvt_bf16x2(b, a);
    unsigned l = cvt_bf16x2(b - f_hi(h), a - f_lo(h));
    *(unsigned*)(g_wh + row * CH + col2) = h;
    *(unsigned*)(g_wl + row * CH + col2) = l;
    if (i < 320)
        g_bqkv[i] = (i < 256) ? bv[i] : (i < 288) ? bq[i - 256] : bk[i - 288];
}

// ============================================================================
// Kernel P2: x [b][c][n] fp32 -> x^T [b][n][c] bf16 hi/lo, ldmatrix-swizzled
// ============================================================================
__global__ void __launch_bounds__(256)
xprep_kernel(const float* __restrict__ x)
{
    __shared__ __align__(16) float xs[CH * 33];
    const int b   = blockIdx.y;
    const int n0  = blockIdx.x * 32;
    const int tid = threadIdx.x;

    const float* xb = x + (size_t)b * CH * NN + n0;
    for (int idx = tid; idx < CH * 32; idx += 256) {
        int c = idx >> 5, n = idx & 31;
        xs[c * 33 + n] = xb[(size_t)c * NN + n];
    }
    __syncthreads();

    const int n   = tid & 31;
    const int g3  = tid >> 5;
    const int nsw = (n0 + n) & 7;
    __nv_bfloat16* dh = g_xh + ((size_t)b * NN + n0 + n) * CH;
    __nv_bfloat16* dl = g_xl + ((size_t)b * NN + n0 + n) * CH;

#pragma unroll
    for (int cc = 0; cc < 4; cc++) {
        int ch = g3 * 4 + cc;
        float v[8];
#pragma unroll
        for (int j = 0; j < 8; j++) v[j] = xs[(ch * 8 + j) * 33 + n];
        unsigned h[4], l[4];
#pragma unroll
        for (int j = 0; j < 4; j++) {
            h[j] = cvt_bf16x2(v[2 * j + 1], v[2 * j]);
            l[j] = cvt_bf16x2(v[2 * j + 1] - f_hi(h[j]), v[2 * j] - f_lo(h[j]));
        }
        int mch = (ch ^ nsw) << 3;
        *(uint4*)(dh + mch) = make_uint4(h[0], h[1], h[2], h[3]);
        *(uint4*)(dl + mch) = make_uint4(l[0], l[1], l[2], l[3]);
    }
}

// ============================================================================
// Kernel P3: fused q/k/v projection via HMMA; V stored as fp16 single.
// ============================================================================
__global__ void __launch_bounds__(320, 1)
qkv_kernel()
{
    extern __shared__ __align__(1024) char smem[];
    const uint32_t sb  = smem_u32(smem);
    const uint32_t mb0 = sb;

    const int tid  = threadIdx.x;
    const int w    = tid >> 5;
    const int lane = tid & 31;
    const int g    = lane >> 2;
    const int t    = lane & 3;
    const int b    = blockIdx.y;
    const int n0   = blockIdx.x * 128;
    const int c0   = w * 32;

    if (tid == 0) MBAR_INIT(mb0, 1);
    __syncthreads();
    if (tid == 0) {
        MBAR_EXPECT_TX(mb0, 131072);
        bulk_g2s(sb + 1024,         g_xh + ((size_t)b * NN + n0) * CH, 65536, mb0);
        bulk_g2s(sb + 1024 + 65536, g_xl + ((size_t)b * NN + n0) * CH, 65536, mb0);
    }

    float d[2][16][4];
#pragma unroll
    for (int mb = 0; mb < 2; mb++)
#pragma unroll
        for (int nb = 0; nb < 16; nb++) {
            d[mb][nb][0] = 0.f; d[mb][nb][1] = 0.f;
            d[mb][nb][2] = 0.f; d[mb][nb][3] = 0.f;
        }

    const uint32_t b_row = sb + 1024
        + (uint32_t)(((lane >> 4) * 8 + (lane & 7)) * 512);
    const int chsel = (lane >> 3) & 1;
    const int r7 = lane & 7;

    unsigned ah[2][2][4], al[2][2][4];
    load_a_frags(ah[0], al[0], g_wh, g_wl, c0, g, t, 0);

    mbar_wait(mb0, 0);
    __syncthreads();

#pragma unroll
    for (int ks = 0; ks < 16; ks++) {
        const int cur = ks & 1, nxt = cur ^ 1;
        if (ks < 15)
            load_a_frags(ah[nxt], al[nxt], g_wh, g_wl, c0, g, t, ks + 1);

        const uint32_t sw = (uint32_t)(((2 * ks + chsel) ^ r7) * 16);
#pragma unroll
        for (int p = 0; p < 8; p++) {
            uint32_t addr = b_row + (uint32_t)(p * 16 * 512) + sw;
            unsigned bh0, bh1, bh2, bh3, bl0, bl1, bl2, bl3;
            ldsm4(bh0, bh1, bh2, bh3, addr);
            ldsm4(bl0, bl1, bl2, bl3, addr + 65536);
            GEMM_P_GROUP(d, ah[cur], al[cur],
                         bh0, bh1, bh2, bh3, bl0, bl1, bl2, bl3, p);
        }
    }

    // ---- epilogue: scatter to V fp16 (warps 0-7), q (warp 8), K (warp 9) ----
    const size_t kvbase = (size_t)b * NTILES * KV_TILE_EL;
#pragma unroll
    for (int mb = 0; mb < 2; mb++) {
        int rA = c0 + mb * 16 + g;
        int rB = rA + 8;
        float biasA = g_bqkv[rA], biasB = g_bqkv[rB];
#pragma unroll
        for (int nb = 0; nb < 16; nb++) {
            int n    = n0 + nb * 8 + t * 2;
            int tile = n >> 6;
            int jt   = n & 63;
            size_t kvb = kvbase + (size_t)tile * KV_TILE_EL;
            float vA0 = d[mb][nb][0] + biasA, vA1 = d[mb][nb][1] + biasA;
            float vB0 = d[mb][nb][2] + biasB, vB1 = d[mb][nb][3] + biasB;
            if (w < 8) {
                size_t vb = kvb + 5120;
                size_t offA = (size_t)rA * 64 + (((jt >> 3) ^ (rA & 7)) << 3) + (jt & 7);
                *(unsigned*)(g_kv + vb + offA) = cvt_f16x2(vA1, vA0);
                size_t offB = (size_t)rB * 64 + (((jt >> 3) ^ (rB & 7)) << 3) + (jt & 7);
                *(unsigned*)(g_kv + vb + offB) = cvt_f16x2(vB1, vB0);
            } else if (w == 8) {
                int dA = rA - 256, dB = rB - 256;
                size_t r0 = ((size_t)b * NN + n) * CQK;
                size_t r1 = r0 + CQK;
                __nv_bfloat16 hA0 = __float2bfloat16(vA0);
                __nv_bfloat16 hA1 = __float2bfloat16(vA1);
                g_qh[r0 + dA] = hA0; g_ql[r0 + dA] = __float2bfloat16(vA0 - __bfloat162float(hA0));
                g_qh[r1 + dA] = hA1; g_ql[r1 + dA] = __float2bfloat16(vA1 - __bfloat162float(hA1));
                __nv_bfloat16 hB0 = __float2bfloat16(vB0);
                __nv_bfloat16 hB1 = __float2bfloat16(vB1);
                g_qh[r0 + dB] = hB0; g_ql[r0 + dB] = __float2bfloat16(vB0 - __bfloat162float(hB0));
                g_qh[r1 + dB] = hB1; g_ql[r1 + dB] = __float2bfloat16(vB1 - __bfloat162float(hB1));
            } else {
                int dA = rA - 288, dB = rB - 288;
                size_t k0 = kvb + (size_t)jt * KPAD;
                size_t k1 = k0 + KPAD;
                __nv_bfloat16 hA0 = __float2bfloat16(vA0);
                __nv_bfloat16 hA1 = __float2bfloat16(vA1);
                g_kv[k0 + dA] = hA0; g_kv[k0 + 2560 + dA] = __float2bfloat16(vA0 - __bfloat162float(hA0));
                g_kv[k1 + dA] = hA1; g_kv[k1 + 2560 + dA] = __float2bfloat16(vA1 - __bfloat162float(hA1));
                __nv_bfloat16 hB0 = __float2bfloat16(vB0);
                __nv_bfloat16 hB1 = __float2bfloat16(vB1);
                g_kv[k0 + dB] = hB0; g_kv[k0 + 2560 + dB] = __float2bfloat16(vB0 - __bfloat162float(hB0));
                g_kv[k1 + dB] = hB1; g_kv[k1 + 2560 + dB] = __float2bfloat16(vB1 - __bfloat162float(hB1));
            }
        }
    }
}

// ============================================================================
// Kernel P4: row max of energies (1-pass bf16 QK). Writes g_rmax[b][n].
// ============================================================================
__global__ void __launch_bounds__(256, 1)
rowmax_kernel()
{
    extern __shared__ __align__(1024) char smem[];
    const uint32_t sb  = smem_u32(smem);
    const uint32_t mb0 = sb + SM_MB0;
    const uint32_t mb1 = sb + SM_MB1;

    const int tid  = threadIdx.x;
    const int w    = tid >> 5;
    const int lane = tid & 31;
    const int g    = lane >> 2;
    const int t    = lane & 3;
    const int b    = blockIdx.y;
    const int q0   = blockIdx.x * TQ;
    const int row0 = q0 + w * 16 + g;

    if (tid == 0) { MBAR_INIT(mb0, 1); MBAR_INIT(mb1, 1); }
    __syncthreads();

    const __nv_bfloat16* kv_src = g_kv + (size_t)b * NTILES * KV_TILE_EL;
    const uint32_t k_lm = (uint32_t)(((lane & 7) * KPAD + (lane >> 3) * 8) * 2);

    unsigned qh[2][4];
    {
        const __nv_bfloat16* qhp = g_qh + (size_t)b * NN * CQK;
#pragma unroll
        for (int kq = 0; kq < 2; kq++) {
            int c0 = kq * 16 + t * 2;
            qh[kq][0] = *(const unsigned*)(qhp + (size_t)row0 * CQK + c0);
            qh[kq][1] = *(const unsigned*)(qhp + (size_t)(row0 + 8) * CQK + c0);
            qh[kq][2] = *(const unsigned*)(qhp + (size_t)row0 * CQK + c0 + 8);
            qh[kq][3] = *(const unsigned*)(qhp + (size_t)(row0 + 8) * CQK + c0 + 8);
        }
    }

    float m0 = -1e30f, m1 = -1e30f;

    if (tid == 0) {
        MBAR_EXPECT_TX(mb0, 5120);
        bulk_g2s(sb + SM_BUF, kv_src, 5120, mb0);
    }

    for (int tl = 0; tl < NTILES; tl++) {
        if (tl + 1 < NTILES && tid == 0) {
            uint32_t mb = ((tl + 1) & 1) ? mb1 : mb0;
            MBAR_EXPECT_TX(mb, 5120);
            bulk_g2s(sb + SM_BUF + ((tl + 1) & 1) * 5120,
                     kv_src + (size_t)(tl + 1) * KV_TILE_EL, 5120, mb);
        }
        mbar_wait((tl & 1) ? mb1 : mb0, (tl >> 1) & 1);

        const uint32_t khb = sb + SM_BUF + (tl & 1) * 5120 + k_lm;

#pragma unroll
        for (int jb = 0; jb < 8; jb++) {
            unsigned kh0, kh1, kh2, kh3;
            ldsm4(kh0, kh1, kh2, kh3, khb + (uint32_t)(jb * 8 * KPAD * 2));
            float sA[4] = {0.f, 0.f, 0.f, 0.f};
            float sB[4] = {0.f, 0.f, 0.f, 0.f};
            mma_bf16(sA, qh[0], kh0, kh1);
            mma_bf16(sB, qh[1], kh2, kh3);
            m0 = fmaxf(m0, fmaxf(sA[0] + sB[0], sA[1] + sB[1]));
            m1 = fmaxf(m1, fmaxf(sA[2] + sB[2], sA[3] + sB[3]));
        }
        __syncthreads();
    }

    m0 = fmaxf(m0, __shfl_xor_sync(0xffffffffu, m0, 1));
    m0 = fmaxf(m0, __shfl_xor_sync(0xffffffffu, m0, 2));
    m1 = fmaxf(m1, __shfl_xor_sync(0xffffffffu, m1, 1));
    m1 = fmaxf(m1, __shfl_xor_sync(0xffffffffu, m1, 2));
    if (t == 0) {
        g_rmax[(size_t)b * NN + row0]     = m0;
        g_rmax[(size_t)b * NN + row0 + 8] = m1;
    }
}

// ============================================================================
// Kernel 3: fused attention + output projection + residual.
// Phase A: flash attention (QK 3-pass bf16, PV 1-pass fp16), ao -> SMEM.
// Phase B: y = x + bg + wg @ ao  (HMMA, ao from SMEM).
// ============================================================================
__global__ void __launch_bounds__(256, 1)
attn_kernel(const float* __restrict__ x,
            const float* __restrict__ bg,
            float* __restrict__ y)
{
    extern __shared__ __align__(1024) char smem[];

    const int tid  = threadIdx.x;
    const int w    = tid >> 5;
    const int lane = tid & 31;
    const int g    = lane >> 2;
    const int t    = lane & 3;
    const int b    = blockIdx.y;
    const int q0   = blockIdx.x * TQ;
    const int row0 = q0 + w * 16 + g;

    const uint32_t sb  = smem_u32(smem);
    const uint32_t mb0 = sb + SM_MB0;
    const uint32_t mb1 = sb + SM_MB1;

    if (tid == 0) { MBAR_INIT(mb0, 1); MBAR_INIT(mb1, 1); }
    __syncthreads();

    const __nv_bfloat16* kv_src = g_kv + (size_t)b * NTILES * KV_TILE_EL;

    const uint32_t k_lm = (uint32_t)(((lane & 7) * KPAD + (lane >> 3) * 8) * 2);
    const int vm = lane >> 3;
    const int vr = lane & 7;
    const uint32_t v_row = (uint32_t)(((vm >> 1) * 8 + vr) * 128);

    const float gm0 = g_rmax[(size_t)b * NN + row0];
    const float gm1 = g_rmax[(size_t)b * NN + row0 + 8];

    unsigned qh[2][4], ql[2][4];
    {
        const __nv_bfloat16* qhp = g_qh + (size_t)b * NN * CQK;
        const __nv_bfloat16* qlp = g_ql + (size_t)b * NN * CQK;
#pragma unroll
        for (int kq = 0; kq < 2; kq++) {
            int c0 = kq * 16 + t * 2;
            qh[kq][0] = *(const unsigned*)(qhp + (size_t)row0 * CQK + c0);
            qh[kq][1] = *(const unsigned*)(qhp + (size_t)(row0 + 8) * CQK + c0);
            qh[kq][2] = *(const unsigned*)(qhp + (size_t)row0 * CQK + c0 + 8);
            qh[kq][3] = *(const unsigned*)(qhp + (size_t)(row0 + 8) * CQK + c0 + 8);
            ql[kq][0] = *(const unsigned*)(qlp + (size_t)row0 * CQK + c0);
            ql[kq][1] = *(const unsigned*)(qlp + (size_t)(row0 + 8) * CQK + c0);
            ql[kq][2] = *(const unsigned*)(qlp + (size_t)row0 * CQK + c0 + 8);
            ql[kq][3] = *(const unsigned*)(qlp + (size_t)(row0 + 8) * CQK + c0 + 8);
        }
    }

    float o[32][4];
#pragma unroll
    for (int cb = 0; cb < 32; cb++) {
        o[cb][0] = 0.f; o[cb][1] = 0.f; o[cb][2] = 0.f; o[cb][3] = 0.f;
    }
    float rs0 = 0.f, rs1 = 0.f;

    if (tid == 0) {
        MBAR_EXPECT_TX(mb0, KV_TILE_B);
        bulk_g2s(sb + SM_BUF, kv_src, KV_TILE_B, mb0);
    }

    float s[2][4][4];

    for (int tl = 0; tl < NTILES; tl++) {
        if (tl + 1 < NTILES && tid == 0) {
            uint32_t mb = ((tl + 1) & 1) ? mb1 : mb0;
            MBAR_EXPECT_TX(mb, KV_TILE_B);
            bulk_g2s(sb + SM_BUF + ((tl + 1) & 1) * KV_TILE_B,
                     kv_src + (size_t)(tl + 1) * KV_TILE_EL, KV_TILE_B, mb);
        }
        mbar_wait((tl & 1) ? mb1 : mb0, (tl >> 1) & 1);
        __syncthreads();

        const uint32_t bb  = sb + SM_BUF + (tl & 1) * KV_TILE_B;
        const uint32_t khb = bb + KH_OFF + k_lm;
        const uint32_t klb = bb + KL_OFF + k_lm;
        const uint32_t vhb = bb + V_OFF + v_row;

        // ---- QK(0) prologue ----
#pragma unroll
        for (int a = 0; a < 4; a++)
#pragma unroll
            for (int i = 0; i < 4; i++) s[0][a][i] = 0.f;
#pragma unroll
        for (int jbi = 0; jbi < 2; jbi++) {
            const uint32_t koff = (uint32_t)(jbi * 8 * KPAD * 2);
            unsigned kh0, kh1, kh2, kh3, kl0, kl1, kl2, kl3;
            ldsm4(kh0, kh1, kh2, kh3, khb + koff);
            ldsm4(kl0, kl1, kl2, kl3, klb + koff);
            float* sa = s[0][jbi * 2];
            float* sc = s[0][jbi * 2 + 1];
            mma_bf16(sa, qh[0], kh0, kh1);
            mma_bf16(sc, qh[1], kh2, kh3);
            mma_bf16(sa, qh[0], kl0, kl1);
            mma_bf16(sc, qh[1], kl2, kl3);
            mma_bf16(sa, ql[0], kh0, kh1);
            mma_bf16(sc, ql[1], kh2, kh3);
        }

#pragma unroll
        for (int kb = 0; kb < 4; kb++) {
            const int cur = kb & 1, nxt = cur ^ 1;

            if (kb < 3) {
#pragma unroll
                for (int a = 0; a < 4; a++)
#pragma unroll
                    for (int i = 0; i < 4; i++) s[nxt][a][i] = 0.f;
#pragma unroll
                for (int jbi = 0; jbi < 2; jbi++) {
                    const uint32_t koff =
                        (uint32_t)(((kb + 1) * 2 + jbi) * 8 * KPAD * 2);
                    unsigned kh0, kh1, kh2, kh3, kl0, kl1, kl2, kl3;
                    ldsm4(kh0, kh1, kh2, kh3, khb + koff);
                    ldsm4(kl0, kl1, kl2, kl3, klb + koff);
                    float* sa = s[nxt][jbi * 2];
                    float* sc = s[nxt][jbi * 2 + 1];
                    mma_bf16(sa, qh[0], kh0, kh1);
                    mma_bf16(sc, qh[1], kh2, kh3);
                    mma_bf16(sa, qh[0], kl0, kl1);
                    mma_bf16(sc, qh[1], kl2, kl3);
                    mma_bf16(sa, ql[0], kh0, kh1);
                    mma_bf16(sc, ql[1], kh2, kh3);
                }
            }

            float* s0a = s[cur][0];
            float* s0b = s[cur][1];
            float* s1a = s[cur][2];
            float* s1b = s[cur][3];
            float e00 = __expf(s0a[0] + s0b[0] - gm0), e01 = __expf(s0a[1] + s0b[1] - gm0);
            float e02 = __expf(s0a[2] + s0b[2] - gm1), e03 = __expf(s0a[3] + s0b[3] - gm1);
            float e10 = __expf(s1a[0] + s1b[0] - gm0), e11 = __expf(s1a[1] + s1b[1] - gm0);
            float e12 = __expf(s1a[2] + s1b[2] - gm1), e13 = __expf(s1a[3] + s1b[3] - gm1);
            rs0 += e00 + e01 + e10 + e11;
            rs1 += e02 + e03 + e12 + e13;

            unsigned pa[4];
            pa[0] = cvt_f16x2(e01, e00);
            pa[1] = cvt_f16x2(e03, e02);
            pa[2] = cvt_f16x2(e11, e10);
            pa[3] = cvt_f16x2(e13, e12);

            const uint32_t vsw = (uint32_t)(((kb * 2 + (vm & 1)) ^ vr) * 16);
            uint32_t avh = vhb + vsw;
#pragma unroll
            for (int p = 0; p < 16; p++) {
                unsigned v0, v1, v2, v3;
                ldsm4(v0, v1, v2, v3, avh);
                mma_f16(o[2 * p],     pa, v0, v1);
                mma_f16(o[2 * p + 1], pa, v2, v3);
                avh += 16 * 128;
            }
        }
        __syncthreads();
    }

    rs0 += __shfl_xor_sync(0xffffffffu, rs0, 1);
    rs0 += __shfl_xor_sync(0xffffffffu, rs0, 2);
    rs1 += __shfl_xor_sync(0xffffffffu, rs1, 1);
    rs1 += __shfl_xor_sync(0xffffffffu, rs1, 2);
    const float inv0 = 1.0f / rs0;
    const float inv1 = 1.0f / rs1;

    // ---- write ao bf16 hi/lo into SMEM (swizzled), local rows ----
    {
        const int lr0 = w * 16 + g;           // local token rows
        const uint32_t r0s = sb + SM_AO_HI + (uint32_t)(lr0 * 512);
        const uint32_t r1s = r0s + 8 * 512;
#pragma unroll
        for (int cb = 0; cb < 32; cb++) {
            uint32_t off = (uint32_t)((((cb ^ g) << 3) + t * 2) * 2);  // bytes
            float v0 = o[cb][0] * inv0, v1 = o[cb][1] * inv0;
            unsigned h = cvt_bf16x2(v1, v0);
            unsigned l = cvt_bf16x2(v1 - f_hi(h), v0 - f_lo(h));
            *(unsigned*)(smem + (r0s - sb) + off)         = h;
            *(unsigned*)(smem + (r0s - sb) + off + 65536) = l;
            float u0 = o[cb][2] * inv1, u1 = o[cb][3] * inv1;
            unsigned h2 = cvt_bf16x2(u1, u0);
            unsigned l2 = cvt_bf16x2(u1 - f_hi(h2), u0 - f_lo(h2));
            *(unsigned*)(smem + (r1s - sb) + off)         = h2;
            *(unsigned*)(smem + (r1s - sb) + off + 65536) = l2;
        }
    }
    __syncthreads();

    // ================= Phase B: output projection + residual ================
    const int n0 = q0;
    const int c0 = w * 32;

    float d[2][16][4];
#pragma unroll
    for (int mb = 0; mb < 2; mb++)
#pragma unroll
        for (int nb = 0; nb < 16; nb++) {
            d[mb][nb][0] = 0.f; d[mb][nb][1] = 0.f;
            d[mb][nb][2] = 0.f; d[mb][nb][3] = 0.f;
        }

    const uint32_t ao_row = sb + SM_AO_HI
        + (uint32_t)(((lane >> 4) * 8 + (lane & 7)) * 512);
    const int chsel = (lane >> 3) & 1;
    const int r7 = lane & 7;

    unsigned ah[2][2][4], al[2][2][4];
    load_a_frags(ah[0], al[0], g_wgh, g_wgl, c0, g, t, 0);

#pragma unroll
    for (int ks = 0; ks < 16; ks++) {
        const int cur = ks & 1, nxt = cur ^ 1;
        if (ks < 15)
            load_a_frags(ah[nxt], al[nxt], g_wgh, g_wgl, c0, g, t, ks + 1);

        const uint32_t sw = (uint32_t)((((2 * ks + chsel) ^ r7)) * 16);
#pragma unroll
        for (int p = 0; p < 8; p++) {
            uint32_t addr = ao_row + (uint32_t)(p * 16 * 512) + sw;
            unsigned bh0, bh1, bh2, bh3, bl0, bl1, bl2, bl3;
            ldsm4(bh0, bh1, bh2, bh3, addr);
            ldsm4(bl0, bl1, bl2, bl3, addr + 65536);
            GEMM_P_GROUP(d, ah[cur], al[cur],
                         bh0, bh1, bh2, bh3, bl0, bl1, bl2, bl3, p);
        }
    }

#pragma unroll
    for (int mb = 0; mb < 2; mb++) {
        int cA = c0 + mb * 16 + g;
        int cB = cA + 8;
        float bgA = bg[cA], bgB = bg[cB];
        const float* xA = x + ((size_t)b * CH + cA) * NN + n0 + t * 2;
        const float* xB = x + ((size_t)b * CH + cB) * NN + n0 + t * 2;
        float* yA = y + ((size_t)b * CH + cA) * NN + n0 + t * 2;
        float* yB = y + ((size_t)b * CH + cB) * NN + n0 + t * 2;
#pragma unroll
        for (int nb = 0; nb < 16; nb++) {
            float2 xr = *(const float2*)(xA + nb * 8);
            *(float2*)(yA + nb * 8) =
                make_float2(xr.x + bgA + d[mb][nb][0],
                            xr.y + bgA + d[mb][nb][1]);
            float2 xs2 = *(const float2*)(xB + nb * 8);
            *(float2*)(yB + nb * 8) =
                make_float2(xs2.x + bgB + d[mb][nb][2],
                            xs2.y + bgB + d[mb][nb][3]);
        }
    }
}

// ============================================================================
extern "C" void kernel_launch(void* const* d_in, const int* in_sizes, int n_in,
                              void* d_out, int out_size)
{
    const float* x  = (const float*)d_in[0];
    const float* wq = (const float*)d_in[1];
    const float* bq = (const float*)d_in[2];
    const float* wk = (const float*)d_in[3];
    const float* bk = (const float*)d_in[4];
    const float* wv = (const float*)d_in[5];
    const float* bv = (const float*)d_in[6];
    const float* wg = (const float*)d_in[7];
    const float* bg = (const float*)d_in[8];
    float* y = (float*)d_out;

    cudaFuncSetAttribute(attn_kernel,
                         cudaFuncAttributeMaxDynamicSharedMemorySize, SM_TOTAL_F);
    cudaFuncSetAttribute(rowmax_kernel,
                         cudaFuncAttributeMaxDynamicSharedMemorySize, RM_SM_TOTAL);
    cudaFuncSetAttribute(qkv_kernel,
                         cudaFuncAttributeMaxDynamicSharedMemorySize, GEMM_SM_TOTAL);

    wgprep_kernel  <<<CH * CH / 512, 256>>>(wg);
    wqkvprep_kernel<<<320 * CH / 512, 256>>>(wv, bv, wq, bq, wk, bk);
    xprep_kernel   <<<dim3(NN / 32, BATCH), 256>>>(x);
    qkv_kernel     <<<dim3(NN / 128, BATCH), 320, GEMM_SM_TOTAL>>>();
    rowmax_kernel  <<<dim3(NN / TQ, BATCH), 256, RM_SM_TOTAL>>>();
    attn_kernel    <<<dim3(NN / TQ, BATCH), 256, SM_TOTAL_F>>>(x, bg, y);
}

// round 17
// speedup vs baseline: 1.7277x; 1.0062x over previous
#include <cuda_runtime.h>
#include <cuda_bf16.h>
#include <cstdint>

#define BATCH 4
#define CH    256
#define CQK   32
#define NN    4096

#define TQ     128
#define TJ     64
#define NTILES (NN / TJ)   // 64

// ---- unified KV tile: [KH 64x40 bf16][KL 64x40 bf16][V 256x64 fp16]
#define KPAD       40
#define KV_TILE_EL 21504
#define KV_TILE_B  43008
#define K_REGION_B 10240                  // KH+KL only (rowmax pass)
#define KH_OFF     0
#define KL_OFF     5120
#define V_OFF      10240
#define SM_MB0  0
#define SM_MB1  8
#define SM_BUF  1024
// fused attn SMEM: [mbar 1024][AO hi 64KB | AO lo 64KB], KV buffers overlay AO
#define SM_AO_HI   1024
#define SM_TOTAL_F (1024 + 131072)      // 132096

// qkv kernel SMEM: [mbar pad 1024][B_hi 64KB][B_lo 64KB]
#define GEMM_SM_TOTAL (1024 + 2 * 65536)

// ---------------- scratch (device globals; no allocation allowed) ----------
__device__ __nv_bfloat16 g_qh[(size_t)BATCH * NN * CQK];
__device__ __nv_bfloat16 g_ql[(size_t)BATCH * NN * CQK];
__device__ __align__(128) __nv_bfloat16 g_kv[(size_t)BATCH * NTILES * KV_TILE_EL];
__device__ __align__(128) __nv_bfloat16 g_xh[(size_t)BATCH * NN * CH];   // x^T swizzled
__device__ __align__(128) __nv_bfloat16 g_xl[(size_t)BATCH * NN * CH];
__device__ __nv_bfloat16 g_wgh[CH * CH];
__device__ __nv_bfloat16 g_wgl[CH * CH];
__device__ __nv_bfloat16 g_wh[320 * CH];   // [wv;wq;wk] hi
__device__ __nv_bfloat16 g_wl[320 * CH];
__device__ float         g_bqkv[320];

// ---------------- helpers ---------------------------------------------------
__device__ __forceinline__ unsigned cvt_bf16x2(float hi, float lo) {
    unsigned r;
    asm("cvt.rn.bf16x2.f32 %0, %1, %2;" : "=r"(r) : "f"(hi), "f"(lo));
    return r;
}
__device__ __forceinline__ unsigned cvt_f16x2(float hi, float lo) {
    unsigned r;
    asm("cvt.rn.f16x2.f32 %0, %1, %2;" : "=r"(r) : "f"(hi), "f"(lo));
    return r;
}
__device__ __forceinline__ float f_lo(unsigned u) { return __uint_as_float(u << 16); }
__device__ __forceinline__ float f_hi(unsigned u) { return __uint_as_float(u & 0xffff0000u); }

__device__ __forceinline__ uint32_t smem_u32(const void* p) {
    uint32_t a;
    asm("{ .reg .u64 t; cvta.to.shared.u64 t, %1; cvt.u32.u64 %0, t; }"
        : "=r"(a) : "l"(p));
    return a;
}

#define MBAR_INIT(addr, cnt) \
    asm volatile("mbarrier.init.shared.b64 [%0], %1;" :: "r"(addr), "r"(cnt) : "memory")
#define MBAR_EXPECT_TX(addr, bytes) \
    asm volatile("mbarrier.arrive.expect_tx.shared.b64 _, [%0], %1;" \
                 :: "r"(addr), "r"(bytes) : "memory")

__device__ __forceinline__ void mbar_wait(uint32_t addr, uint32_t parity) {
    asm volatile(
        "{\n\t.reg .pred P;\n\t"
        "WL_%=:\n\t"
        "mbarrier.try_wait.parity.acquire.cta.shared::cta.b64 P, [%0], %1, 0x989680;\n\t"
        "@P bra WD_%=;\n\t"
        "bra WL_%=;\n\t"
        "WD_%=:\n\t}"
        :: "r"(addr), "r"(parity) : "memory");
}
__device__ __forceinline__ void bulk_g2s(uint32_t dst, const void* src,
                                         uint32_t bytes, uint32_t mbar) {
    asm volatile(
        "cp.async.bulk.shared::cluster.global.mbarrier::complete_tx::bytes "
        "[%0], [%1], %2, [%3];"
        :: "r"(dst), "l"(src), "r"(bytes), "r"(mbar) : "memory");
}

__device__ __forceinline__ void ldsm4(unsigned& r0, unsigned& r1,
                                      unsigned& r2, unsigned& r3, uint32_t a) {
    asm volatile("ldmatrix.sync.aligned.m8n8.x4.shared.b16 {%0,%1,%2,%3}, [%4];"
                 : "=r"(r0), "=r"(r1), "=r"(r2), "=r"(r3) : "r"(a));
}

__device__ __forceinline__ void mma_bf16(float* d, const unsigned* a,
                                         unsigned b0, unsigned b1) {
    asm volatile(
        "mma.sync.aligned.m16n8k16.row.col.f32.bf16.bf16.f32 "
        "{%0,%1,%2,%3}, {%4,%5,%6,%7}, {%8,%9}, {%0,%1,%2,%3};"
        : "+f"(d[0]), "+f"(d[1]), "+f"(d[2]), "+f"(d[3])
        : "r"(a[0]), "r"(a[1]), "r"(a[2]), "r"(a[3]), "r"(b0), "r"(b1));
}
__device__ __forceinline__ void mma_f16(float* d, const unsigned* a,
                                        unsigned b0, unsigned b1) {
    asm volatile(
        "mma.sync.aligned.m16n8k16.row.col.f32.f16.f16.f32 "
        "{%0,%1,%2,%3}, {%4,%5,%6,%7}, {%8,%9}, {%0,%1,%2,%3};"
        : "+f"(d[0]), "+f"(d[1]), "+f"(d[2]), "+f"(d[3])
        : "r"(a[0]), "r"(a[1]), "r"(a[2]), "r"(a[3]), "r"(b0), "r"(b1));
}

// load A fragments (weights) for k-slice ks
__device__ __forceinline__ void load_a_frags(
    unsigned ah[2][4], unsigned al[2][4],
    const __nv_bfloat16* wh, const __nv_bfloat16* wl,
    int c0, int g, int t, int ks)
{
#pragma unroll
    for (int mb = 0; mb < 2; mb++) {
        int cr  = c0 + mb * 16 + g;
        int col = ks * 16 + t * 2;
        ah[mb][0] = *(const unsigned*)(wh + cr * CH + col);
        ah[mb][1] = *(const unsigned*)(wh + (cr + 8) * CH + col);
        ah[mb][2] = *(const unsigned*)(wh + cr * CH + col + 8);
        ah[mb][3] = *(const unsigned*)(wh + (cr + 8) * CH + col + 8);
        al[mb][0] = *(const unsigned*)(wl + cr * CH + col);
        al[mb][1] = *(const unsigned*)(wl + (cr + 8) * CH + col);
        al[mb][2] = *(const unsigned*)(wl + cr * CH + col + 8);
        al[mb][3] = *(const unsigned*)(wl + (cr + 8) * CH + col + 8);
    }
}

// 12 MMAs for one p-group
#define GEMM_P_GROUP(d, ah, al, bh0, bh1, bh2, bh3, bl0, bl1, bl2, bl3, p) \
    do {                                                                   \
        mma_bf16(d[0][2*(p)],     ah[0], bh0, bh1);                        \
        mma_bf16(d[0][2*(p) + 1], ah[0], bh2, bh3);                        \
        mma_bf16(d[1][2*(p)],     ah[1], bh0, bh1);                        \
        mma_bf16(d[1][2*(p) + 1], ah[1], bh2, bh3);                        \
        mma_bf16(d[0][2*(p)],     ah[0], bl0, bl1);                        \
        mma_bf16(d[0][2*(p) + 1], ah[0], bl2, bl3);                        \
        mma_bf16(d[1][2*(p)],     ah[1], bl0, bl1);                        \
        mma_bf16(d[1][2*(p) + 1], ah[1], bl2, bl3);                        \
        mma_bf16(d[0][2*(p)],     al[0], bh0, bh1);                        \
        mma_bf16(d[0][2*(p) + 1], al[0], bh2, bh3);                        \
        mma_bf16(d[1][2*(p)],     al[1], bh0, bh1);                        \
        mma_bf16(d[1][2*(p) + 1], al[1], bh2, bh3);                        \
    } while (0)

// ============================================================================
// Kernel P0: merged weight prep. Blocks 0-127: wg. Blocks 128-287: [wv;wq;wk].
// ============================================================================
__global__ void __launch_bounds__(256)
wprep_kernel(const float* __restrict__ wg,
             const float* __restrict__ wv, const float* __restrict__ bv,
             const float* __restrict__ wq, const float* __restrict__ bq,
             const float* __restrict__ wk, const float* __restrict__ bk)
{
    const int blk = blockIdx.x;
    if (blk < 128) {
        int i = blk * 256 + threadIdx.x;
        float a = wg[2 * i], b = wg[2 * i + 1];
        unsigned h = cvt_bf16x2(b, a);
        unsigned l = cvt_bf16x2(b - f_hi(h), a - f_lo(h));
        *(unsigned*)(g_wgh + 2 * i) = h;
        *(unsigned*)(g_wgl + 2 * i) = l;
    } else {
        int i = (blk - 128) * 256 + threadIdx.x;
        int row  = i >> 7;
        int col2 = (i & 127) * 2;
        const float* src = (row < 256) ? wv + row * CH
                         : (row < 288) ? wq + (row - 256) * CH
                                       : wk + (row - 288) * CH;
        float a = src[col2], b = src[col2 + 1];
        unsigned h = cvt_bf16x2(b, a);
        unsigned l = cvt_bf16x2(b - f_hi(h), a - f_lo(h));
        *(unsigned*)(g_wh + row * CH + col2) = h;
        *(unsigned*)(g_wl + row * CH + col2) = l;
        if (i < 320)
            g_bqkv[i] = (i < 256) ? bv[i] : (i < 288) ? bq[i - 256] : bk[i - 288];
    }
}

// ============================================================================
// Kernel P2: x [b][c][n] fp32 -> x^T [b][n][c] bf16 hi/lo, ldmatrix-swizzled
// ============================================================================
__global__ void __launch_bounds__(256)
xprep_kernel(const float* __restrict__ x)
{
    __shared__ __align__(16) float xs[CH * 33];
    const int b   = blockIdx.y;
    const int n0  = blockIdx.x * 32;
    const int tid = threadIdx.x;

    const float* xb = x + (size_t)b * CH * NN + n0;
    for (int idx = tid; idx < CH * 32; idx += 256) {
        int c = idx >> 5, n = idx & 31;
        xs[c * 33 + n] = xb[(size_t)c * NN + n];
    }
    __syncthreads();

    const int n   = tid & 31;
    const int g3  = tid >> 5;
    const int nsw = (n0 + n) & 7;
    __nv_bfloat16* dh = g_xh + ((size_t)b * NN + n0 + n) * CH;
    __nv_bfloat16* dl = g_xl + ((size_t)b * NN + n0 + n) * CH;

#pragma unroll
    for (int cc = 0; cc < 4; cc++) {
        int ch = g3 * 4 + cc;
        float v[8];
#pragma unroll
        for (int j = 0; j < 8; j++) v[j] = xs[(ch * 8 + j) * 33 + n];
        unsigned h[4], l[4];
#pragma unroll
        for (int j = 0; j < 4; j++) {
            h[j] = cvt_bf16x2(v[2 * j + 1], v[2 * j]);
            l[j] = cvt_bf16x2(v[2 * j + 1] - f_hi(h[j]), v[2 * j] - f_lo(h[j]));
        }
        int mch = (ch ^ nsw) << 3;
        *(uint4*)(dh + mch) = make_uint4(h[0], h[1], h[2], h[3]);
        *(uint4*)(dl + mch) = make_uint4(l[0], l[1], l[2], l[3]);
    }
}

// ============================================================================
// Kernel P3: fused q/k/v projection via HMMA; V stored as fp16 single.
// ============================================================================
__global__ void __launch_bounds__(320, 1)
qkv_kernel()
{
    extern __shared__ __align__(1024) char smem[];
    const uint32_t sb  = smem_u32(smem);
    const uint32_t mb0 = sb;

    const int tid  = threadIdx.x;
    const int w    = tid >> 5;
    const int lane = tid & 31;
    const int g    = lane >> 2;
    const int t    = lane & 3;
    const int b    = blockIdx.y;
    const int n0   = blockIdx.x * 128;
    const int c0   = w * 32;

    if (tid == 0) MBAR_INIT(mb0, 1);
    __syncthreads();
    if (tid == 0) {
        MBAR_EXPECT_TX(mb0, 131072);
        bulk_g2s(sb + 1024,         g_xh + ((size_t)b * NN + n0) * CH, 65536, mb0);
        bulk_g2s(sb + 1024 + 65536, g_xl + ((size_t)b * NN + n0) * CH, 65536, mb0);
    }

    float d[2][16][4];
#pragma unroll
    for (int mb = 0; mb < 2; mb++)
#pragma unroll
        for (int nb = 0; nb < 16; nb++) {
            d[mb][nb][0] = 0.f; d[mb][nb][1] = 0.f;
            d[mb][nb][2] = 0.f; d[mb][nb][3] = 0.f;
        }

    const uint32_t b_row = sb + 1024
        + (uint32_t)(((lane >> 4) * 8 + (lane & 7)) * 512);
    const int chsel = (lane >> 3) & 1;
    const int r7 = lane & 7;

    unsigned ah[2][2][4], al[2][2][4];
    load_a_frags(ah[0], al[0], g_wh, g_wl, c0, g, t, 0);

    mbar_wait(mb0, 0);
    __syncthreads();

#pragma unroll
    for (int ks = 0; ks < 16; ks++) {
        const int cur = ks & 1, nxt = cur ^ 1;
        if (ks < 15)
            load_a_frags(ah[nxt], al[nxt], g_wh, g_wl, c0, g, t, ks + 1);

        const uint32_t sw = (uint32_t)(((2 * ks + chsel) ^ r7) * 16);
#pragma unroll
        for (int p = 0; p < 8; p++) {
            uint32_t addr = b_row + (uint32_t)(p * 16 * 512) + sw;
            unsigned bh0, bh1, bh2, bh3, bl0, bl1, bl2, bl3;
            ldsm4(bh0, bh1, bh2, bh3, addr);
            ldsm4(bl0, bl1, bl2, bl3, addr + 65536);
            GEMM_P_GROUP(d, ah[cur], al[cur],
                         bh0, bh1, bh2, bh3, bl0, bl1, bl2, bl3, p);
        }
    }

    // ---- epilogue: scatter to V fp16 (warps 0-7), q (warp 8), K (warp 9) ----
    const size_t kvbase = (size_t)b * NTILES * KV_TILE_EL;
#pragma unroll
    for (int mb = 0; mb < 2; mb++) {
        int rA = c0 + mb * 16 + g;
        int rB = rA + 8;
        float biasA = g_bqkv[rA], biasB = g_bqkv[rB];
#pragma unroll
        for (int nb = 0; nb < 16; nb++) {
            int n    = n0 + nb * 8 + t * 2;
            int tile = n >> 6;
            int jt   = n & 63;
            size_t kvb = kvbase + (size_t)tile * KV_TILE_EL;
            float vA0 = d[mb][nb][0] + biasA, vA1 = d[mb][nb][1] + biasA;
            float vB0 = d[mb][nb][2] + biasB, vB1 = d[mb][nb][3] + biasB;
            if (w < 8) {
                size_t vb = kvb + 5120;
                size_t offA = (size_t)rA * 64 + (((jt >> 3) ^ (rA & 7)) << 3) + (jt & 7);
                *(unsigned*)(g_kv + vb + offA) = cvt_f16x2(vA1, vA0);
                size_t offB = (size_t)rB * 64 + (((jt >> 3) ^ (rB & 7)) << 3) + (jt & 7);
                *(unsigned*)(g_kv + vb + offB) = cvt_f16x2(vB1, vB0);
            } else if (w == 8) {
                int dA = rA - 256, dB = rB - 256;
                size_t r0 = ((size_t)b * NN + n) * CQK;
                size_t r1 = r0 + CQK;
                __nv_bfloat16 hA0 = __float2bfloat16(vA0);
                __nv_bfloat16 hA1 = __float2bfloat16(vA1);
                g_qh[r0 + dA] = hA0; g_ql[r0 + dA] = __float2bfloat16(vA0 - __bfloat162float(hA0));
                g_qh[r1 + dA] = hA1; g_ql[r1 + dA] = __float2bfloat16(vA1 - __bfloat162float(hA1));
                __nv_bfloat16 hB0 = __float2bfloat16(vB0);
                __nv_bfloat16 hB1 = __float2bfloat16(vB1);
                g_qh[r0 + dB] = hB0; g_ql[r0 + dB] = __float2bfloat16(vB0 - __bfloat162float(hB0));
                g_qh[r1 + dB] = hB1; g_ql[r1 + dB] = __float2bfloat16(vB1 - __bfloat162float(hB1));
            } else {
                int dA = rA - 288, dB = rB - 288;
                size_t k0 = kvb + (size_t)jt * KPAD;
                size_t k1 = k0 + KPAD;
                __nv_bfloat16 hA0 = __float2bfloat16(vA0);
                __nv_bfloat16 hA1 = __float2bfloat16(vA1);
                g_kv[k0 + dA] = hA0; g_kv[k0 + 2560 + dA] = __float2bfloat16(vA0 - __bfloat162float(hA0));
                g_kv[k1 + dA] = hA1; g_kv[k1 + 2560 + dA] = __float2bfloat16(vA1 - __bfloat162float(hA1));
                __nv_bfloat16 hB0 = __float2bfloat16(vB0);
                __nv_bfloat16 hB1 = __float2bfloat16(vB1);
                g_kv[k0 + dB] = hB0; g_kv[k0 + 2560 + dB] = __float2bfloat16(vB0 - __bfloat162float(hB0));
                g_kv[k1 + dB] = hB1; g_kv[k1 + 2560 + dB] = __float2bfloat16(vB1 - __bfloat162float(hB1));
            }
        }
    }
}

// ============================================================================
// Kernel 3: fused rowmax + attention + output projection + residual.
// Phase 0: rowmax (1-pass bf16 QK, K-only staging).
// Phase A: flash attention (QK 3-pass bf16, PV 1-pass fp16), ao -> SMEM.
// Phase B: y = x + bg + wg @ ao  (HMMA, ao from SMEM).
// ============================================================================
__global__ void __launch_bounds__(256, 1)
attn_kernel(const float* __restrict__ x,
            const float* __restrict__ bg,
            float* __restrict__ y)
{
    extern __shared__ __align__(1024) char smem[];

    const int tid  = threadIdx.x;
    const int w    = tid >> 5;
    const int lane = tid & 31;
    const int g    = lane >> 2;
    const int t    = lane & 3;
    const int b    = blockIdx.y;
    const int q0   = blockIdx.x * TQ;
    const int row0 = q0 + w * 16 + g;

    const uint32_t sb  = smem_u32(smem);
    const uint32_t mb0 = sb + SM_MB0;
    const uint32_t mb1 = sb + SM_MB1;

    if (tid == 0) { MBAR_INIT(mb0, 1); MBAR_INIT(mb1, 1); }
    __syncthreads();

    const __nv_bfloat16* kv_src = g_kv + (size_t)b * NTILES * KV_TILE_EL;

    const uint32_t k_lm = (uint32_t)(((lane & 7) * KPAD + (lane >> 3) * 8) * 2);
    const int vm = lane >> 3;
    const int vr = lane & 7;
    const uint32_t v_row = (uint32_t)(((vm >> 1) * 8 + vr) * 128);

    unsigned qh[2][4], ql[2][4];
    {
        const __nv_bfloat16* qhp = g_qh + (size_t)b * NN * CQK;
        const __nv_bfloat16* qlp = g_ql + (size_t)b * NN * CQK;
#pragma unroll
        for (int kq = 0; kq < 2; kq++) {
            int c0 = kq * 16 + t * 2;
            qh[kq][0] = *(const unsigned*)(qhp + (size_t)row0 * CQK + c0);
            qh[kq][1] = *(const unsigned*)(qhp + (size_t)(row0 + 8) * CQK + c0);
            qh[kq][2] = *(const unsigned*)(qhp + (size_t)row0 * CQK + c0 + 8);
            qh[kq][3] = *(const unsigned*)(qhp + (size_t)(row0 + 8) * CQK + c0 + 8);
            ql[kq][0] = *(const unsigned*)(qlp + (size_t)row0 * CQK + c0);
            ql[kq][1] = *(const unsigned*)(qlp + (size_t)(row0 + 8) * CQK + c0);
            ql[kq][2] = *(const unsigned*)(qlp + (size_t)row0 * CQK + c0 + 8);
            ql[kq][3] = *(const unsigned*)(qlp + (size_t)(row0 + 8) * CQK + c0 + 8);
        }
    }

    // ================= Phase 0: rowmax (K-only staging) =====================
    float gm0 = -1e30f, gm1 = -1e30f;
    if (tid == 0) {
        MBAR_EXPECT_TX(mb0, K_REGION_B);
        bulk_g2s(sb + SM_BUF, kv_src, K_REGION_B, mb0);
    }
    for (int tl = 0; tl < NTILES; tl++) {
        if (tl + 1 < NTILES && tid == 0) {
            uint32_t mb = ((tl + 1) & 1) ? mb1 : mb0;
            MBAR_EXPECT_TX(mb, K_REGION_B);
            bulk_g2s(sb + SM_BUF + ((tl + 1) & 1) * KV_TILE_B,
                     kv_src + (size_t)(tl + 1) * KV_TILE_EL, K_REGION_B, mb);
        }
        mbar_wait((tl & 1) ? mb1 : mb0, (tl >> 1) & 1);

        const uint32_t khb = sb + SM_BUF + (tl & 1) * KV_TILE_B + k_lm;
#pragma unroll
        for (int jb = 0; jb < 8; jb++) {
            unsigned kh0, kh1, kh2, kh3;
            ldsm4(kh0, kh1, kh2, kh3, khb + (uint32_t)(jb * 8 * KPAD * 2));
            float sA[4] = {0.f, 0.f, 0.f, 0.f};
            float sB[4] = {0.f, 0.f, 0.f, 0.f};
            mma_bf16(sA, qh[0], kh0, kh1);
            mma_bf16(sB, qh[1], kh2, kh3);
            gm0 = fmaxf(gm0, fmaxf(sA[0] + sB[0], sA[1] + sB[1]));
            gm1 = fmaxf(gm1, fmaxf(sA[2] + sB[2], sA[3] + sB[3]));
        }
        __syncthreads();
    }
    gm0 = fmaxf(gm0, __shfl_xor_sync(0xffffffffu, gm0, 1));
    gm0 = fmaxf(gm0, __shfl_xor_sync(0xffffffffu, gm0, 2));
    gm1 = fmaxf(gm1, __shfl_xor_sync(0xffffffffu, gm1, 1));
    gm1 = fmaxf(gm1, __shfl_xor_sync(0xffffffffu, gm1, 2));

    // ================= Phase A: flash attention =============================
    float o[32][4];
#pragma unroll
    for (int cb = 0; cb < 32; cb++) {
        o[cb][0] = 0.f; o[cb][1] = 0.f; o[cb][2] = 0.f; o[cb][3] = 0.f;
    }
    float rs0 = 0.f, rs1 = 0.f;

    // stage counter continues: s = 64 + tl (parities continue seamlessly)
    if (tid == 0) {
        MBAR_EXPECT_TX(mb0, KV_TILE_B);     // s=64 -> mb0, parity (64>>1)&1 = 0
        bulk_g2s(sb + SM_BUF, kv_src, KV_TILE_B, mb0);
    }

    float s[2][4][4];

    for (int tl = 0; tl < NTILES; tl++) {
        const int st = 64 + tl;
        if (tl + 1 < NTILES && tid == 0) {
            const int sn = st + 1;
            uint32_t mb = (sn & 1) ? mb1 : mb0;
            MBAR_EXPECT_TX(mb, KV_TILE_B);
            bulk_g2s(sb + SM_BUF + (sn & 1) * KV_TILE_B,
                     kv_src + (size_t)(tl + 1) * KV_TILE_EL, KV_TILE_B, mb);
        }
        mbar_wait((st & 1) ? mb1 : mb0, (st >> 1) & 1);
        __syncthreads();

        const uint32_t bb  = sb + SM_BUF + (st & 1) * KV_TILE_B;
        const uint32_t khb = bb + KH_OFF + k_lm;
        const uint32_t klb = bb + KL_OFF + k_lm;
        const uint32_t vhb = bb + V_OFF + v_row;

        // ---- QK(0) prologue ----
#pragma unroll
        for (int a = 0; a < 4; a++)
#pragma unroll
            for (int i = 0; i < 4; i++) s[0][a][i] = 0.f;
#pragma unroll
        for (int jbi = 0; jbi < 2; jbi++) {
            const uint32_t koff = (uint32_t)(jbi * 8 * KPAD * 2);
            unsigned kh0, kh1, kh2, kh3, kl0, kl1, kl2, kl3;
            ldsm4(kh0, kh1, kh2, kh3, khb + koff);
            ldsm4(kl0, kl1, kl2, kl3, klb + koff);
            float* sa = s[0][jbi * 2];
            float* sc = s[0][jbi * 2 + 1];
            mma_bf16(sa, qh[0], kh0, kh1);
            mma_bf16(sc, qh[1], kh2, kh3);
            mma_bf16(sa, qh[0], kl0, kl1);
            mma_bf16(sc, qh[1], kl2, kl3);
            mma_bf16(sa, ql[0], kh0, kh1);
            mma_bf16(sc, ql[1], kh2, kh3);
        }

#pragma unroll
        for (int kb = 0; kb < 4; kb++) {
            const int cur = kb & 1, nxt = cur ^ 1;

            if (kb < 3) {
#pragma unroll
                for (int a = 0; a < 4; a++)
#pragma unroll
                    for (int i = 0; i < 4; i++) s[nxt][a][i] = 0.f;
#pragma unroll
                for (int jbi = 0; jbi < 2; jbi++) {
                    const uint32_t koff =
                        (uint32_t)(((kb + 1) * 2 + jbi) * 8 * KPAD * 2);
                    unsigned kh0, kh1, kh2, kh3, kl0, kl1, kl2, kl3;
                    ldsm4(kh0, kh1, kh2, kh3, khb + koff);
                    ldsm4(kl0, kl1, kl2, kl3, klb + koff);
                    float* sa = s[nxt][jbi * 2];
                    float* sc = s[nxt][jbi * 2 + 1];
                    mma_bf16(sa, qh[0], kh0, kh1);
                    mma_bf16(sc, qh[1], kh2, kh3);
                    mma_bf16(sa, qh[0], kl0, kl1);
                    mma_bf16(sc, qh[1], kl2, kl3);
                    mma_bf16(sa, ql[0], kh0, kh1);
                    mma_bf16(sc, ql[1], kh2, kh3);
                }
            }

            float* s0a = s[cur][0];
            float* s0b = s[cur][1];
            float* s1a = s[cur][2];
            float* s1b = s[cur][3];
            float e00 = __expf(s0a[0] + s0b[0] - gm0), e01 = __expf(s0a[1] + s0b[1] - gm0);
            float e02 = __expf(s0a[2] + s0b[2] - gm1), e03 = __expf(s0a[3] + s0b[3] - gm1);
            float e10 = __expf(s1a[0] + s1b[0] - gm0), e11 = __expf(s1a[1] + s1b[1] - gm0);
            float e12 = __expf(s1a[2] + s1b[2] - gm1), e13 = __expf(s1a[3] + s1b[3] - gm1);
            rs0 += e00 + e01 + e10 + e11;
            rs1 += e02 + e03 + e12 + e13;

            unsigned pa[4];
            pa[0] = cvt_f16x2(e01, e00);
            pa[1] = cvt_f16x2(e03, e02);
            pa[2] = cvt_f16x2(e11, e10);
            pa[3] = cvt_f16x2(e13, e12);

            const uint32_t vsw = (uint32_t)(((kb * 2 + (vm & 1)) ^ vr) * 16);
            uint32_t avh = vhb + vsw;
#pragma unroll
            for (int p = 0; p < 16; p++) {
                unsigned v0, v1, v2, v3;
                ldsm4(v0, v1, v2, v3, avh);
                mma_f16(o[2 * p],     pa, v0, v1);
                mma_f16(o[2 * p + 1], pa, v2, v3);
                avh += 16 * 128;
            }
        }
        __syncthreads();
    }

    rs0 += __shfl_xor_sync(0xffffffffu, rs0, 1);
    rs0 += __shfl_xor_sync(0xffffffffu, rs0, 2);
    rs1 += __shfl_xor_sync(0xffffffffu, rs1, 1);
    rs1 += __shfl_xor_sync(0xffffffffu, rs1, 2);
    const float inv0 = 1.0f / rs0;
    const float inv1 = 1.0f / rs1;

    // ---- write ao bf16 hi/lo into SMEM (swizzled), local rows ----
    {
        const int lr0 = w * 16 + g;
        const uint32_t r0off = (uint32_t)(SM_AO_HI - 0) + (uint32_t)(lr0 * 512);
        const uint32_t r1off = r0off + 8 * 512;
#pragma unroll
        for (int cb = 0; cb < 32; cb++) {
            uint32_t off = (uint32_t)((((cb ^ g) << 3) + t * 2) * 2);
            float v0 = o[cb][0] * inv0, v1 = o[cb][1] * inv0;
            unsigned h = cvt_bf16x2(v1, v0);
            unsigned l = cvt_bf16x2(v1 - f_hi(h), v0 - f_lo(h));
            *(unsigned*)(smem + r0off + off)         = h;
            *(unsigned*)(smem + r0off + off + 65536) = l;
            float u0 = o[cb][2] * inv1, u1 = o[cb][3] * inv1;
            unsigned h2 = cvt_bf16x2(u1, u0);
            unsigned l2 = cvt_bf16x2(u1 - f_hi(h2), u0 - f_lo(h2));
            *(unsigned*)(smem + r1off + off)         = h2;
            *(unsigned*)(smem + r1off + off + 65536) = l2;
        }
    }
    __syncthreads();

    // ================= Phase B: output projection + residual ================
    const int n0 = q0;
    const int c0 = w * 32;

    float d[2][16][4];
#pragma unroll
    for (int mb = 0; mb < 2; mb++)
#pragma unroll
        for (int nb = 0; nb < 16; nb++) {
            d[mb][nb][0] = 0.f; d[mb][nb][1] = 0.f;
            d[mb][nb][2] = 0.f; d[mb][nb][3] = 0.f;
        }

    const uint32_t ao_row = sb + SM_AO_HI
        + (uint32_t)(((lane >> 4) * 8 + (lane & 7)) * 512);
    const int chsel = (lane >> 3) & 1;
    const int r7 = lane & 7;

    unsigned ah[2][2][4], al[2][2][4];
    load_a_frags(ah[0], al[0], g_wgh, g_wgl, c0, g, t, 0);

#pragma unroll
    for (int ks = 0; ks < 16; ks++) {
        const int cur = ks & 1, nxt = cur ^ 1;
        if (ks < 15)
            load_a_frags(ah[nxt], al[nxt], g_wgh, g_wgl, c0, g, t, ks + 1);

        const uint32_t sw = (uint32_t)((((2 * ks + chsel) ^ r7)) * 16);
#pragma unroll
        for (int p = 0; p < 8; p++) {
            uint32_t addr = ao_row + (uint32_t)(p * 16 * 512) + sw;
            unsigned bh0, bh1, bh2, bh3, bl0, bl1, bl2, bl3;
            ldsm4(bh0, bh1, bh2, bh3, addr);
            ldsm4(bl0, bl1, bl2, bl3, addr + 65536);
            GEMM_P_GROUP(d, ah[cur], al[cur],
                         bh0, bh1, bh2, bh3, bl0, bl1, bl2, bl3, p);
        }
    }

#pragma unroll
    for (int mb = 0; mb < 2; mb++) {
        int cA = c0 + mb * 16 + g;
        int cB = cA + 8;
        float bgA = bg[cA], bgB = bg[cB];
        const float* xA = x + ((size_t)b * CH + cA) * NN + n0 + t * 2;
        const float* xB = x + ((size_t)b * CH + cB) * NN + n0 + t * 2;
        float* yA = y + ((size_t)b * CH + cA) * NN + n0 + t * 2;
        float* yB = y + ((size_t)b * CH + cB) * NN + n0 + t * 2;
#pragma unroll
        for (int nb = 0; nb < 16; nb++) {
            float2 xr = *(const float2*)(xA + nb * 8);
            *(float2*)(yA + nb * 8) =
                make_float2(xr.x + bgA + d[mb][nb][0],
                            xr.y + bgA + d[mb][nb][1]);
            float2 xs2 = *(const float2*)(xB + nb * 8);
            *(float2*)(yB + nb * 8) =
                make_float2(xs2.x + bgB + d[mb][nb][2],
                            xs2.y + bgB + d[mb][nb][3]);
        }
    }
}

// ============================================================================
extern "C" void kernel_launch(void* const* d_in, const int* in_sizes, int n_in,
                              void* d_out, int out_size)
{
    const float* x  = (const float*)d_in[0];
    const float* wq = (const float*)d_in[1];
    const float* bq = (const float*)d_in[2];
    const float* wk = (const float*)d_in[3];
    const float* bk = (const float*)d_in[4];
    const float* wv = (const float*)d_in[5];
    const float* bv = (const float*)d_in[6];
    const float* wg = (const float*)d_in[7];
    const float* bg = (const float*)d_in[8];
    float* y = (float*)d_out;

    cudaFuncSetAttribute(attn_kernel,
                         cudaFuncAttributeMaxDynamicSharedMemorySize, SM_TOTAL_F);
    cudaFuncSetAttribute(qkv_kernel,
                         cudaFuncAttributeMaxDynamicSharedMemorySize, GEMM_SM_TOTAL);

    wprep_kernel<<<288, 256>>>(wg, wv, bv, wq, bq, wk, bk);
    xprep_kernel<<<dim3(NN / 32, BATCH), 256>>>(x);
    qkv_kernel  <<<dim3(NN / 128, BATCH), 320, GEMM_SM_TOTAL>>>();
    attn_kernel <<<dim3(NN / TQ, BATCH), 256, SM_TOTAL_F>>>(x, bg, y);
}